// round 12
// baseline (speedup 1.0000x reference)
#include <cuda_runtime.h>
#include <math.h>
#include <stdint.h>

#define BATCH   4
#define SEQ     2048
#define DMODEL  512
#define NHEAD   8
#define HDIM    64
#define ROWS    (BATCH * SEQ)        /* 8192 */
#define QKVN    (3 * DMODEL)         /* 1536 */

// Scratch (allocation-free rule: device globals)
__device__ float g_qkv[(size_t)ROWS * QKVN];     // [8192, 1536] tf32 bits
__device__ float g_att[(size_t)ROWS * DMODEL];   // [8192, 512] fp32

__device__ __forceinline__ uint32_t f2tf(float x) {
    uint32_t r;
    asm("cvt.rna.tf32.f32 %0, %1;" : "=r"(r) : "f"(x));
    return r;
}

__device__ __forceinline__ void mma_tf32(float c[4], const uint32_t a[4],
                                         uint32_t b0, uint32_t b1) {
    asm volatile(
        "mma.sync.aligned.m16n8k8.row.col.f32.tf32.tf32.f32 "
        "{%0,%1,%2,%3}, {%4,%5,%6,%7}, {%8,%9}, {%0,%1,%2,%3};"
        : "+f"(c[0]), "+f"(c[1]), "+f"(c[2]), "+f"(c[3])
        : "r"(a[0]), "r"(a[1]), "r"(a[2]), "r"(a[3]), "r"(b0), "r"(b1));
}

__device__ __forceinline__ void cp_async16(uint32_t smem_dst, const void* gsrc) {
    asm volatile("cp.async.cg.shared.global [%0], [%1], 16;"
                 :: "r"(smem_dst), "l"(gsrc) : "memory");
}
__device__ __forceinline__ void cp_async_commit() {
    asm volatile("cp.async.commit_group;" ::: "memory");
}
__device__ __forceinline__ void cp_async_wait1() {
    asm volatile("cp.async.wait_group 1;" ::: "memory");
}

// ---------------------------------------------------------------------------
// TF32 tensor-core GEMM, 2-stage cp.async pipeline (exact R9 version).
// ---------------------------------------------------------------------------
#define GBM 128
#define GBN 128
#define GBK 16
#define APAD 20
#define BPAD 136
#define AW (GBM * APAD)
#define BW (GBK * BPAD)

__global__ __launch_bounds__(256)
void tf32_gemm_kernel(const float* __restrict__ A, const float* __restrict__ B,
                      float* __restrict__ C, int M, int N, int K, int cvt_out) {
    __shared__ float As[2][AW];
    __shared__ float Bs[2][BW];

    const int tid  = threadIdx.x;
    const int warp = tid >> 5;
    const int lane = tid & 31;
    const int g = lane >> 2;
    const int c = lane & 3;
    const int wm = warp >> 2;
    const int wn = warp & 3;

    const int arow = tid >> 1, acol = (tid & 1) << 3;
    const int brow = tid >> 4, bcol = (tid & 15) << 3;

    const float* Ag = A + (size_t)(blockIdx.y * GBM + arow) * K + acol;
    const float* Bg = B + (size_t)brow * N + blockIdx.x * GBN + bcol;

    const uint32_t a_dst[2] = {
        (uint32_t)__cvta_generic_to_shared(&As[0][arow * APAD + acol]),
        (uint32_t)__cvta_generic_to_shared(&As[1][arow * APAD + acol]) };
    const uint32_t b_dst[2] = {
        (uint32_t)__cvta_generic_to_shared(&Bs[0][brow * BPAD + bcol]),
        (uint32_t)__cvta_generic_to_shared(&Bs[1][brow * BPAD + bcol]) };

    float acc[4][4][4];
    #pragma unroll
    for (int mf = 0; mf < 4; mf++)
        #pragma unroll
        for (int nf = 0; nf < 4; nf++)
            #pragma unroll
            for (int j = 0; j < 4; j++) acc[mf][nf][j] = 0.f;

    const int nIter = K / GBK;

    cp_async16(a_dst[0],      Ag);
    cp_async16(a_dst[0] + 16, Ag + 4);
    cp_async16(b_dst[0],      Bg);
    cp_async16(b_dst[0] + 16, Bg + 4);
    cp_async_commit();

    for (int it = 0; it < nIter; it++) {
        const int cur = it & 1, nxt = cur ^ 1;

        if (it + 1 < nIter) {
            const int k0 = (it + 1) * GBK;
            cp_async16(a_dst[nxt],      Ag + k0);
            cp_async16(a_dst[nxt] + 16, Ag + k0 + 4);
            cp_async16(b_dst[nxt],      Bg + (size_t)k0 * N);
            cp_async16(b_dst[nxt] + 16, Bg + (size_t)k0 * N + 4);
        }
        cp_async_commit();
        cp_async_wait1();
        __syncthreads();

        const float* Asc = As[cur];
        const float* Bsc = Bs[cur];

        #pragma unroll
        for (int kk = 0; kk < GBK; kk += 8) {
            uint32_t af[4][4], bf0[4], bf1[4];
            #pragma unroll
            for (int mf = 0; mf < 4; mf++) {
                const int r0 = wm * 64 + mf * 16 + g;
                af[mf][0] = f2tf(Asc[(r0    ) * APAD + kk + c    ]);
                af[mf][1] = f2tf(Asc[(r0 + 8) * APAD + kk + c    ]);
                af[mf][2] = f2tf(Asc[(r0    ) * APAD + kk + c + 4]);
                af[mf][3] = f2tf(Asc[(r0 + 8) * APAD + kk + c + 4]);
            }
            #pragma unroll
            for (int nf = 0; nf < 4; nf++) {
                const int n = wn * 32 + nf * 8 + g;
                bf0[nf] = f2tf(Bsc[(kk + c    ) * BPAD + n]);
                bf1[nf] = f2tf(Bsc[(kk + c + 4) * BPAD + n]);
            }
            #pragma unroll
            for (int mf = 0; mf < 4; mf++)
                #pragma unroll
                for (int nf = 0; nf < 4; nf++)
                    mma_tf32(acc[mf][nf], af[mf], bf0[nf], bf1[nf]);
        }
        __syncthreads();
    }

    #pragma unroll
    for (int mf = 0; mf < 4; mf++) {
        const int r0 = blockIdx.y * GBM + wm * 64 + mf * 16 + g;
        #pragma unroll
        for (int nf = 0; nf < 4; nf++) {
            const int col = blockIdx.x * GBN + wn * 32 + nf * 8 + 2 * c;
            float v0 = acc[mf][nf][0], v1 = acc[mf][nf][1];
            float v2 = acc[mf][nf][2], v3 = acc[mf][nf][3];
            if (cvt_out) {
                v0 = __uint_as_float(f2tf(v0)); v1 = __uint_as_float(f2tf(v1));
                v2 = __uint_as_float(f2tf(v2)); v3 = __uint_as_float(f2tf(v3));
            }
            *(float2*)&C[(size_t)r0 * N + col]       = make_float2(v0, v1);
            *(float2*)&C[(size_t)(r0 + 8) * N + col] = make_float2(v2, v3);
        }
    }
}

// ---------------------------------------------------------------------------
// TF32 flash attention: synchronous staging, TWO 64-key tiles per barrier
// pair. Stage K0/V0/K1/V1 (128 keys) at once (doubled LDG MLP), then compute
// the two tiles back-to-back (same per-tile math/order as the 588us kernel
// -> bit-identical). No extra register state vs the known-good loop.
// ---------------------------------------------------------------------------
#define PAD 72
#define QT  128
#define KVT (64 * PAD)
#define OFF_KV (QT * PAD)                    /* 4 KV buffers: K0 V0 K1 V1 */
#define OFF_MK (OFF_KV + 4 * KVT)            /* 2 mask arrays of 64 floats */
#define ATT_SMEM_WORDS (OFF_MK + 2 * 64)
#define NSTEPS (SEQ / 128)

__global__ __launch_bounds__(256)
void attn_mma_kernel(const uint32_t* __restrict__ qkv, const int* __restrict__ pmask,
                     float* __restrict__ attout) {
    extern __shared__ uint32_t smu[];
    uint32_t* Qs = smu;                      // [QT][PAD]; later reused as Ps
    uint32_t* Kb[2] = { smu + OFF_KV,           smu + OFF_KV + 2 * KVT };
    uint32_t* Vb[2] = { smu + OFF_KV + KVT,     smu + OFF_KV + 3 * KVT };
    float*    mkb   = (float*)(smu + OFF_MK);  // [2][64]

    const int qt = blockIdx.x, h = blockIdx.y, b = blockIdx.z;
    const int tid  = threadIdx.x;
    const int warp = tid >> 5;
    const int lane = tid & 31;
    const int g = lane >> 2;
    const int c = lane & 3;

    const size_t rbase = (size_t)b * (NHEAD * SEQ) + (size_t)h * SEQ;
    const uint32_t* qkv_b = qkv + rbase * (3 * HDIM);

    const int qrow  = tid >> 1;
    const int qhalf = (tid & 1) * 32;
    const int lrow = tid >> 2;
    const int lcol = (tid & 3) << 4;

    // ---- stage Q tile (pure copy, already tf32) ----
    {
        const uint4* src = (const uint4*)(qkv_b + (size_t)(qt * QT + qrow) * (3 * HDIM) + qhalf);
        uint4* dst = (uint4*)&Qs[qrow * PAD + qhalf];
        #pragma unroll
        for (int u = 0; u < 8; u++) dst[u] = src[u];
    }
    __syncthreads();

    // ---- Q fragments ----
    uint32_t qa[8][4];
    {
        const int r0 = warp * 16 + g;
        #pragma unroll
        for (int ch = 0; ch < 8; ch++) {
            qa[ch][0] = Qs[(r0    ) * PAD + ch * 8 + c    ];
            qa[ch][1] = Qs[(r0 + 8) * PAD + ch * 8 + c    ];
            qa[ch][2] = Qs[(r0    ) * PAD + ch * 8 + c + 4];
            qa[ch][3] = Qs[(r0 + 8) * PAD + ch * 8 + c + 4];
        }
    }

    float o[8][4];
    #pragma unroll
    for (int nf = 0; nf < 8; nf++)
        #pragma unroll
        for (int j = 0; j < 4; j++) o[nf][j] = 0.f;
    float m0 = -INFINITY, m1 = -INFINITY, l0 = 0.f, l1 = 0.f;

    uint32_t* Ps = Qs;  // reuse after Q frags are in registers

    for (int st = 0; st < NSTEPS; st++) {
        __syncthreads();   // prior-step reads of Kb/Vb/mkb complete

        // ---- stage 128 keys: K0/V0 (rows st*128..+63), K1/V1 (+64..+127) ----
        {
            const size_t row0 = (size_t)(st * 128 + lrow) * (3 * HDIM);
            const size_t row1 = (size_t)(st * 128 + 64 + lrow) * (3 * HDIM);
            const uint4* s0k = (const uint4*)(qkv_b + row0 + HDIM + lcol);
            const uint4* s0v = (const uint4*)(qkv_b + row0 + 2 * HDIM + lcol);
            const uint4* s1k = (const uint4*)(qkv_b + row1 + HDIM + lcol);
            const uint4* s1v = (const uint4*)(qkv_b + row1 + 2 * HDIM + lcol);
            uint4* d0k = (uint4*)&Kb[0][lrow * PAD + lcol];
            uint4* d0v = (uint4*)&Vb[0][lrow * PAD + lcol];
            uint4* d1k = (uint4*)&Kb[1][lrow * PAD + lcol];
            uint4* d1v = (uint4*)&Vb[1][lrow * PAD + lcol];
            #pragma unroll
            for (int u = 0; u < 4; u++) {
                d0k[u] = s0k[u]; d0v[u] = s0v[u];
                d1k[u] = s1k[u]; d1v[u] = s1v[u];
            }
            if (tid < 128)
                mkb[tid] = (pmask[b * SEQ + st * 128 + tid] != 0) ? 0.f : -INFINITY;
        }
        __syncthreads();

        // ---- two 64-key tiles, same order as the single-tile loop ----
        #pragma unroll
        for (int half = 0; half < 2; half++) {
            const uint32_t* Ks = Kb[half];
            const uint32_t* Vs = Vb[half];
            const float*    mk = mkb + half * 64;

            // ---- S = Q K^T ----
            float s[8][4];
            #pragma unroll
            for (int kg = 0; kg < 8; kg++) {
                s[kg][0] = s[kg][1] = s[kg][2] = s[kg][3] = 0.f;
                const uint32_t* kbase = &Ks[(kg * 8 + g) * PAD + c];
                #pragma unroll
                for (int ch = 0; ch < 8; ch++)
                    mma_tf32(s[kg], qa[ch], kbase[ch * 8], kbase[ch * 8 + 4]);
            }

            // ---- scale + mask ----
            #pragma unroll
            for (int kg = 0; kg < 8; kg++) {
                const int col0 = kg * 8 + 2 * c;
                float mk0 = mk[col0], mk1 = mk[col0 + 1];
                s[kg][0] = s[kg][0] * 0.125f + mk0;
                s[kg][1] = s[kg][1] * 0.125f + mk1;
                s[kg][2] = s[kg][2] * 0.125f + mk0;
                s[kg][3] = s[kg][3] * 0.125f + mk1;
            }

            // ---- online softmax ----
            float mx0 = -INFINITY, mx1 = -INFINITY;
            #pragma unroll
            for (int kg = 0; kg < 8; kg++) {
                mx0 = fmaxf(mx0, fmaxf(s[kg][0], s[kg][1]));
                mx1 = fmaxf(mx1, fmaxf(s[kg][2], s[kg][3]));
            }
            mx0 = fmaxf(mx0, __shfl_xor_sync(0xffffffffu, mx0, 1));
            mx0 = fmaxf(mx0, __shfl_xor_sync(0xffffffffu, mx0, 2));
            mx1 = fmaxf(mx1, __shfl_xor_sync(0xffffffffu, mx1, 1));
            mx1 = fmaxf(mx1, __shfl_xor_sync(0xffffffffu, mx1, 2));

            float mn0 = fmaxf(m0, mx0), mn1 = fmaxf(m1, mx1);
            float sc0 = (mn0 == -INFINITY) ? 1.f : __expf(m0 - mn0);
            float sc1 = (mn1 == -INFINITY) ? 1.f : __expf(m1 - mn1);

            float sum0 = 0.f, sum1 = 0.f;
            {
                const int r0 = warp * 16 + g;
                uint32_t* pdst0 = &Ps[(r0    ) * PAD + 2 * c];
                uint32_t* pdst1 = &Ps[(r0 + 8) * PAD + 2 * c];
                #pragma unroll
                for (int kg = 0; kg < 8; kg++) {
                    float p0 = (s[kg][0] == -INFINITY) ? 0.f : __expf(s[kg][0] - mn0);
                    float p1 = (s[kg][1] == -INFINITY) ? 0.f : __expf(s[kg][1] - mn0);
                    float p2 = (s[kg][2] == -INFINITY) ? 0.f : __expf(s[kg][2] - mn1);
                    float p3 = (s[kg][3] == -INFINITY) ? 0.f : __expf(s[kg][3] - mn1);
                    uint32_t t0 = f2tf(p0), t1 = f2tf(p1), t2 = f2tf(p2), t3 = f2tf(p3);
                    sum0 += __uint_as_float(t0) + __uint_as_float(t1);
                    sum1 += __uint_as_float(t2) + __uint_as_float(t3);
                    *(uint2*)(pdst0 + kg * 8) = make_uint2(t0, t1);
                    *(uint2*)(pdst1 + kg * 8) = make_uint2(t2, t3);
                }
            }
            sum0 += __shfl_xor_sync(0xffffffffu, sum0, 1);
            sum0 += __shfl_xor_sync(0xffffffffu, sum0, 2);
            sum1 += __shfl_xor_sync(0xffffffffu, sum1, 1);
            sum1 += __shfl_xor_sync(0xffffffffu, sum1, 2);

            l0 = l0 * sc0 + sum0;  m0 = mn0;
            l1 = l1 * sc1 + sum1;  m1 = mn1;

            #pragma unroll
            for (int nf = 0; nf < 8; nf++) {
                o[nf][0] *= sc0; o[nf][1] *= sc0;
                o[nf][2] *= sc1; o[nf][3] *= sc1;
            }
            __syncwarp();   // Ps rows are warp-private

            // ---- O += P V ----
            #pragma unroll
            for (int ch = 0; ch < 8; ch++) {
                uint32_t pa[4];
                const int r0 = warp * 16 + g;
                pa[0] = Ps[(r0    ) * PAD + ch * 8 + c    ];
                pa[1] = Ps[(r0 + 8) * PAD + ch * 8 + c    ];
                pa[2] = Ps[(r0    ) * PAD + ch * 8 + c + 4];
                pa[3] = Ps[(r0 + 8) * PAD + ch * 8 + c + 4];
                const uint32_t* vb0 = &Vs[(ch * 8 + c    ) * PAD + g];
                const uint32_t* vb1 = &Vs[(ch * 8 + c + 4) * PAD + g];
                #pragma unroll
                for (int nf = 0; nf < 8; nf++)
                    mma_tf32(o[nf], pa, vb0[nf * 8], vb1[nf * 8]);
            }
            __syncwarp();
        }
    }

    // ---- epilogue ----
    {
        const int r0 = warp * 16 + g;
        const int row0 = qt * QT + r0, row1 = row0 + 8;
        float inv0 = (l0 > 0.f) ? (1.f / l0) : 0.f;
        float inv1 = (l1 > 0.f) ? (1.f / l1) : 0.f;
        if (pmask[b * SEQ + row0] == 0) inv0 = 0.f;
        if (pmask[b * SEQ + row1] == 0) inv1 = 0.f;
        float* out0 = attout + (rbase + row0) * HDIM + 2 * c;
        float* out1 = attout + (rbase + row1) * HDIM + 2 * c;
        #pragma unroll
        for (int nf = 0; nf < 8; nf++) {
            *(float2*)(out0 + nf * 8) = make_float2(o[nf][0] * inv0, o[nf][1] * inv0);
            *(float2*)(out1 + nf * 8) = make_float2(o[nf][2] * inv1, o[nf][3] * inv1);
        }
    }
}

// ---------------------------------------------------------------------------
extern "C" void kernel_launch(void* const* d_in, const int* in_sizes, int n_in,
                              void* d_out, int out_size) {
    const float* x     = (const float*)d_in[0];
    const int*   pmask = (const int*)d_in[2];
    const float* Wqkv  = (const float*)d_in[3];
    const float* Wout  = (const float*)d_in[4];
    float* out = (float*)d_out;

    float *qkv_p = nullptr, *att_p = nullptr;
    cudaGetSymbolAddress((void**)&qkv_p, g_qkv);
    cudaGetSymbolAddress((void**)&att_p, g_att);

    const int attn_smem = ATT_SMEM_WORDS * (int)sizeof(uint32_t);
    cudaFuncSetAttribute(attn_mma_kernel, cudaFuncAttributeMaxDynamicSharedMemorySize, attn_smem);

    // 1) QKV = x @ W_qkv : [8192,512] @ [512,1536]  (output tf32-rounded bits)
    tf32_gemm_kernel<<<dim3(QKVN / GBN, ROWS / GBM), 256>>>(x, Wqkv, qkv_p, ROWS, QKVN, DMODEL, 1);

    // 2) tf32 tensor-core attention over the reshaped (flat) layout
    attn_mma_kernel<<<dim3(SEQ / QT, NHEAD, BATCH), 256, attn_smem>>>(
        (const uint32_t*)qkv_p, pmask, att_p);

    // 3) out = att @ W_out : [8192,512] @ [512,512]  (plain fp32 output)
    tf32_gemm_kernel<<<dim3(DMODEL / GBN, ROWS / GBM), 256>>>(att_p, Wout, out, ROWS, DMODEL, DMODEL, 0);
}

// round 13
// speedup vs baseline: 1.2072x; 1.2072x over previous
#include <cuda_runtime.h>
#include <math.h>
#include <stdint.h>

#define BATCH   4
#define SEQ     2048
#define DMODEL  512
#define NHEAD   8
#define HDIM    64
#define ROWS    (BATCH * SEQ)        /* 8192 */
#define QKVN    (3 * DMODEL)         /* 1536 */

// Scratch (allocation-free rule: device globals)
__device__ float g_qkv[(size_t)ROWS * QKVN];     // [8192, 1536] tf32 bits
__device__ float g_att[(size_t)ROWS * DMODEL];   // [8192, 512] fp32

__device__ __forceinline__ uint32_t f2tf(float x) {
    uint32_t r;
    asm("cvt.rna.tf32.f32 %0, %1;" : "=r"(r) : "f"(x));
    return r;
}

__device__ __forceinline__ void mma_tf32(float c[4], const uint32_t a[4],
                                         uint32_t b0, uint32_t b1) {
    asm volatile(
        "mma.sync.aligned.m16n8k8.row.col.f32.tf32.tf32.f32 "
        "{%0,%1,%2,%3}, {%4,%5,%6,%7}, {%8,%9}, {%0,%1,%2,%3};"
        : "+f"(c[0]), "+f"(c[1]), "+f"(c[2]), "+f"(c[3])
        : "r"(a[0]), "r"(a[1]), "r"(a[2]), "r"(a[3]), "r"(b0), "r"(b1));
}

__device__ __forceinline__ void cp_async16(uint32_t smem_dst, const void* gsrc) {
    asm volatile("cp.async.cg.shared.global [%0], [%1], 16;"
                 :: "r"(smem_dst), "l"(gsrc) : "memory");
}
__device__ __forceinline__ void cp_async_commit() {
    asm volatile("cp.async.commit_group;" ::: "memory");
}
__device__ __forceinline__ void cp_async_wait2() {
    asm volatile("cp.async.wait_group 2;" ::: "memory");
}

// ---------------------------------------------------------------------------
// TF32 tensor-core GEMM, 3-stage cp.async pipeline (R9 compute structure,
// one extra buffer; wait_group 2 keeps two tiles in flight).
// C[M,N] = A[M,K] @ B[K,N], row-major. 128x128x16 block tile, 8 warps,
// 64x32 warp tile. f2tf at fragment load. cvt_out != 0: C tf32-rounded.
// ---------------------------------------------------------------------------
#define GBM 128
#define GBN 128
#define GBK 16
#define APAD 20
#define BPAD 136
#define AW (GBM * APAD)
#define BW (GBK * BPAD)

__global__ __launch_bounds__(256)
void tf32_gemm_kernel(const float* __restrict__ A, const float* __restrict__ B,
                      float* __restrict__ C, int M, int N, int K, int cvt_out) {
    __shared__ float As[3][AW];
    __shared__ float Bs[3][BW];

    const int tid  = threadIdx.x;
    const int warp = tid >> 5;
    const int lane = tid & 31;
    const int g = lane >> 2;
    const int c = lane & 3;
    const int wm = warp >> 2;
    const int wn = warp & 3;

    const int arow = tid >> 1, acol = (tid & 1) << 3;
    const int brow = tid >> 4, bcol = (tid & 15) << 3;

    const float* Ag = A + (size_t)(blockIdx.y * GBM + arow) * K + acol;
    const float* Bg = B + (size_t)brow * N + blockIdx.x * GBN + bcol;

    const uint32_t a_dst[3] = {
        (uint32_t)__cvta_generic_to_shared(&As[0][arow * APAD + acol]),
        (uint32_t)__cvta_generic_to_shared(&As[1][arow * APAD + acol]),
        (uint32_t)__cvta_generic_to_shared(&As[2][arow * APAD + acol]) };
    const uint32_t b_dst[3] = {
        (uint32_t)__cvta_generic_to_shared(&Bs[0][brow * BPAD + bcol]),
        (uint32_t)__cvta_generic_to_shared(&Bs[1][brow * BPAD + bcol]),
        (uint32_t)__cvta_generic_to_shared(&Bs[2][brow * BPAD + bcol]) };

    float acc[4][4][4];
    #pragma unroll
    for (int mf = 0; mf < 4; mf++)
        #pragma unroll
        for (int nf = 0; nf < 4; nf++)
            #pragma unroll
            for (int j = 0; j < 4; j++) acc[mf][nf][j] = 0.f;

    const int nIter = K / GBK;   // >= 2 for all our shapes

    // prologue: prefetch tiles 0 and 1 (one commit group each)
    cp_async16(a_dst[0],      Ag);
    cp_async16(a_dst[0] + 16, Ag + 4);
    cp_async16(b_dst[0],      Bg);
    cp_async16(b_dst[0] + 16, Bg + 4);
    cp_async_commit();
    {
        const int k0 = GBK;
        cp_async16(a_dst[1],      Ag + k0);
        cp_async16(a_dst[1] + 16, Ag + k0 + 4);
        cp_async16(b_dst[1],      Bg + (size_t)k0 * N);
        cp_async16(b_dst[1] + 16, Bg + (size_t)k0 * N + 4);
        cp_async_commit();
    }

    for (int it = 0; it < nIter; it++) {
        const int cur = it % 3;

        // prefetch tile it+2 into buffer (it+2)%3; always commit (may be empty)
        if (it + 2 < nIter) {
            const int nxt = (it + 2) % 3;
            const int k0 = (it + 2) * GBK;
            cp_async16(a_dst[nxt],      Ag + k0);
            cp_async16(a_dst[nxt] + 16, Ag + k0 + 4);
            cp_async16(b_dst[nxt],      Bg + (size_t)k0 * N);
            cp_async16(b_dst[nxt] + 16, Bg + (size_t)k0 * N + 4);
        }
        cp_async_commit();
        cp_async_wait2();      // tile `it` complete; tiles it+1, it+2 may fly
        __syncthreads();

        const float* Asc = As[cur];
        const float* Bsc = Bs[cur];

        #pragma unroll
        for (int kk = 0; kk < GBK; kk += 8) {
            uint32_t af[4][4], bf0[4], bf1[4];
            #pragma unroll
            for (int mf = 0; mf < 4; mf++) {
                const int r0 = wm * 64 + mf * 16 + g;
                af[mf][0] = f2tf(Asc[(r0    ) * APAD + kk + c    ]);
                af[mf][1] = f2tf(Asc[(r0 + 8) * APAD + kk + c    ]);
                af[mf][2] = f2tf(Asc[(r0    ) * APAD + kk + c + 4]);
                af[mf][3] = f2tf(Asc[(r0 + 8) * APAD + kk + c + 4]);
            }
            #pragma unroll
            for (int nf = 0; nf < 4; nf++) {
                const int n = wn * 32 + nf * 8 + g;
                bf0[nf] = f2tf(Bsc[(kk + c    ) * BPAD + n]);
                bf1[nf] = f2tf(Bsc[(kk + c + 4) * BPAD + n]);
            }
            #pragma unroll
            for (int mf = 0; mf < 4; mf++)
                #pragma unroll
                for (int nf = 0; nf < 4; nf++)
                    mma_tf32(acc[mf][nf], af[mf], bf0[nf], bf1[nf]);
        }
        __syncthreads();   // all reads of `cur` done before its refill (issued at it+1)
    }

    #pragma unroll
    for (int mf = 0; mf < 4; mf++) {
        const int r0 = blockIdx.y * GBM + wm * 64 + mf * 16 + g;
        #pragma unroll
        for (int nf = 0; nf < 4; nf++) {
            const int col = blockIdx.x * GBN + wn * 32 + nf * 8 + 2 * c;
            float v0 = acc[mf][nf][0], v1 = acc[mf][nf][1];
            float v2 = acc[mf][nf][2], v3 = acc[mf][nf][3];
            if (cvt_out) {
                v0 = __uint_as_float(f2tf(v0)); v1 = __uint_as_float(f2tf(v1));
                v2 = __uint_as_float(f2tf(v2)); v3 = __uint_as_float(f2tf(v3));
            }
            *(float2*)&C[(size_t)r0 * N + col]       = make_float2(v0, v1);
            *(float2*)&C[(size_t)(r0 + 8) * N + col] = make_float2(v2, v3);
        }
    }
}

// ---------------------------------------------------------------------------
// TF32 tensor-core flash attention — EXACT R9 (588us) configuration.
// Block = 256 threads (8 warps), 128 queries of one (b,h'); streams 64-key
// tiles. qkv holds pre-rounded tf32 bits -> staging is pure vectorized copy.
// P round-trips through smem warp-locally (reuses Q region).
// ---------------------------------------------------------------------------
#define PAD 72
#define QT  128
#define ATT_SMEM_WORDS (QT * PAD + 2 * 64 * PAD + 64)

__global__ __launch_bounds__(256)
void attn_mma_kernel(const uint32_t* __restrict__ qkv, const int* __restrict__ pmask,
                     float* __restrict__ attout) {
    extern __shared__ uint32_t smu[];
    uint32_t* Qs = smu;                  // [QT][PAD]; later reused as Ps
    uint32_t* Ks = Qs + QT * PAD;        // [64][PAD]
    uint32_t* Vs = Ks + 64 * PAD;        // [64][PAD]
    float*    mk = (float*)(Vs + 64 * PAD);  // [64]

    const int qt = blockIdx.x, h = blockIdx.y, b = blockIdx.z;
    const int tid  = threadIdx.x;
    const int warp = tid >> 5;
    const int lane = tid & 31;
    const int g = lane >> 2;
    const int c = lane & 3;

    const size_t rbase = (size_t)b * (NHEAD * SEQ) + (size_t)h * SEQ;
    const uint32_t* qkv_b = qkv + rbase * (3 * HDIM);

    const int qrow  = tid >> 1;
    const int qhalf = (tid & 1) * 32;
    const int lrow = tid >> 2;
    const int lcol = (tid & 3) << 4;

    // ---- stage Q tile (pure copy, already tf32) ----
    {
        const uint4* src = (const uint4*)(qkv_b + (size_t)(qt * QT + qrow) * (3 * HDIM) + qhalf);
        uint4* dst = (uint4*)&Qs[qrow * PAD + qhalf];
        #pragma unroll
        for (int u = 0; u < 8; u++) dst[u] = src[u];
    }
    __syncthreads();

    // ---- Q fragments ----
    uint32_t qa[8][4];
    {
        const int r0 = warp * 16 + g;
        #pragma unroll
        for (int ch = 0; ch < 8; ch++) {
            qa[ch][0] = Qs[(r0    ) * PAD + ch * 8 + c    ];
            qa[ch][1] = Qs[(r0 + 8) * PAD + ch * 8 + c    ];
            qa[ch][2] = Qs[(r0    ) * PAD + ch * 8 + c + 4];
            qa[ch][3] = Qs[(r0 + 8) * PAD + ch * 8 + c + 4];
        }
    }

    float o[8][4];
    #pragma unroll
    for (int nf = 0; nf < 8; nf++)
        #pragma unroll
        for (int j = 0; j < 4; j++) o[nf][j] = 0.f;
    float m0 = -INFINITY, m1 = -INFINITY, l0 = 0.f, l1 = 0.f;

    uint32_t* Ps = Qs;  // reuse after Q frags are in registers

    for (int kt = 0; kt < SEQ / 64; kt++) {
        __syncthreads();   // prior-iteration reads of Ks/Vs/mk complete

        // ---- stage K, V tiles (pure copy) + mask ----
        {
            const uint4* srck = (const uint4*)(qkv_b + (size_t)(kt * 64 + lrow) * (3 * HDIM) + HDIM + lcol);
            const uint4* srcv = (const uint4*)(qkv_b + (size_t)(kt * 64 + lrow) * (3 * HDIM) + 2 * HDIM + lcol);
            uint4* dk = (uint4*)&Ks[lrow * PAD + lcol];
            uint4* dv = (uint4*)&Vs[lrow * PAD + lcol];
            #pragma unroll
            for (int u = 0; u < 4; u++) { dk[u] = srck[u]; dv[u] = srcv[u]; }
            if (tid < 64)
                mk[tid] = (pmask[b * SEQ + kt * 64 + tid] != 0) ? 0.f : -INFINITY;
        }
        __syncthreads();

        // ---- S = Q K^T ----
        float s[8][4];
        #pragma unroll
        for (int kg = 0; kg < 8; kg++) {
            s[kg][0] = s[kg][1] = s[kg][2] = s[kg][3] = 0.f;
            const uint32_t* kbase = &Ks[(kg * 8 + g) * PAD + c];
            #pragma unroll
            for (int ch = 0; ch < 8; ch++)
                mma_tf32(s[kg], qa[ch], kbase[ch * 8], kbase[ch * 8 + 4]);
        }

        // ---- scale + mask ----
        #pragma unroll
        for (int kg = 0; kg < 8; kg++) {
            const int col0 = kg * 8 + 2 * c;
            float mk0 = mk[col0], mk1 = mk[col0 + 1];
            s[kg][0] = s[kg][0] * 0.125f + mk0;
            s[kg][1] = s[kg][1] * 0.125f + mk1;
            s[kg][2] = s[kg][2] * 0.125f + mk0;
            s[kg][3] = s[kg][3] * 0.125f + mk1;
        }

        // ---- online softmax ----
        float mx0 = -INFINITY, mx1 = -INFINITY;
        #pragma unroll
        for (int kg = 0; kg < 8; kg++) {
            mx0 = fmaxf(mx0, fmaxf(s[kg][0], s[kg][1]));
            mx1 = fmaxf(mx1, fmaxf(s[kg][2], s[kg][3]));
        }
        mx0 = fmaxf(mx0, __shfl_xor_sync(0xffffffffu, mx0, 1));
        mx0 = fmaxf(mx0, __shfl_xor_sync(0xffffffffu, mx0, 2));
        mx1 = fmaxf(mx1, __shfl_xor_sync(0xffffffffu, mx1, 1));
        mx1 = fmaxf(mx1, __shfl_xor_sync(0xffffffffu, mx1, 2));

        float mn0 = fmaxf(m0, mx0), mn1 = fmaxf(m1, mx1);
        float sc0 = (mn0 == -INFINITY) ? 1.f : __expf(m0 - mn0);
        float sc1 = (mn1 == -INFINITY) ? 1.f : __expf(m1 - mn1);

        float sum0 = 0.f, sum1 = 0.f;
        {
            const int r0 = warp * 16 + g;
            uint32_t* pdst0 = &Ps[(r0    ) * PAD + 2 * c];
            uint32_t* pdst1 = &Ps[(r0 + 8) * PAD + 2 * c];
            #pragma unroll
            for (int kg = 0; kg < 8; kg++) {
                float p0 = (s[kg][0] == -INFINITY) ? 0.f : __expf(s[kg][0] - mn0);
                float p1 = (s[kg][1] == -INFINITY) ? 0.f : __expf(s[kg][1] - mn0);
                float p2 = (s[kg][2] == -INFINITY) ? 0.f : __expf(s[kg][2] - mn1);
                float p3 = (s[kg][3] == -INFINITY) ? 0.f : __expf(s[kg][3] - mn1);
                uint32_t t0 = f2tf(p0), t1 = f2tf(p1), t2 = f2tf(p2), t3 = f2tf(p3);
                sum0 += __uint_as_float(t0) + __uint_as_float(t1);
                sum1 += __uint_as_float(t2) + __uint_as_float(t3);
                *(uint2*)(pdst0 + kg * 8) = make_uint2(t0, t1);
                *(uint2*)(pdst1 + kg * 8) = make_uint2(t2, t3);
            }
        }
        sum0 += __shfl_xor_sync(0xffffffffu, sum0, 1);
        sum0 += __shfl_xor_sync(0xffffffffu, sum0, 2);
        sum1 += __shfl_xor_sync(0xffffffffu, sum1, 1);
        sum1 += __shfl_xor_sync(0xffffffffu, sum1, 2);

        l0 = l0 * sc0 + sum0;  m0 = mn0;
        l1 = l1 * sc1 + sum1;  m1 = mn1;

        #pragma unroll
        for (int nf = 0; nf < 8; nf++) {
            o[nf][0] *= sc0; o[nf][1] *= sc0;
            o[nf][2] *= sc1; o[nf][3] *= sc1;
        }
        __syncwarp();   // Ps rows are warp-private

        // ---- O += P V ----
        #pragma unroll
        for (int ch = 0; ch < 8; ch++) {
            uint32_t pa[4];
            const int r0 = warp * 16 + g;
            pa[0] = Ps[(r0    ) * PAD + ch * 8 + c    ];
            pa[1] = Ps[(r0 + 8) * PAD + ch * 8 + c    ];
            pa[2] = Ps[(r0    ) * PAD + ch * 8 + c + 4];
            pa[3] = Ps[(r0 + 8) * PAD + ch * 8 + c + 4];
            const uint32_t* vb0 = &Vs[(ch * 8 + c    ) * PAD + g];
            const uint32_t* vb1 = &Vs[(ch * 8 + c + 4) * PAD + g];
            #pragma unroll
            for (int nf = 0; nf < 8; nf++)
                mma_tf32(o[nf], pa, vb0[nf * 8], vb1[nf * 8]);
        }
        __syncwarp();
    }

    // ---- epilogue ----
    {
        const int r0 = warp * 16 + g;
        const int row0 = qt * QT + r0, row1 = row0 + 8;
        float inv0 = (l0 > 0.f) ? (1.f / l0) : 0.f;
        float inv1 = (l1 > 0.f) ? (1.f / l1) : 0.f;
        if (pmask[b * SEQ + row0] == 0) inv0 = 0.f;
        if (pmask[b * SEQ + row1] == 0) inv1 = 0.f;
        float* out0 = attout + (rbase + row0) * HDIM + 2 * c;
        float* out1 = attout + (rbase + row1) * HDIM + 2 * c;
        #pragma unroll
        for (int nf = 0; nf < 8; nf++) {
            *(float2*)(out0 + nf * 8) = make_float2(o[nf][0] * inv0, o[nf][1] * inv0);
            *(float2*)(out1 + nf * 8) = make_float2(o[nf][2] * inv1, o[nf][3] * inv1);
        }
    }
}

// ---------------------------------------------------------------------------
extern "C" void kernel_launch(void* const* d_in, const int* in_sizes, int n_in,
                              void* d_out, int out_size) {
    const float* x     = (const float*)d_in[0];
    const int*   pmask = (const int*)d_in[2];
    const float* Wqkv  = (const float*)d_in[3];
    const float* Wout  = (const float*)d_in[4];
    float* out = (float*)d_out;

    float *qkv_p = nullptr, *att_p = nullptr;
    cudaGetSymbolAddress((void**)&qkv_p, g_qkv);
    cudaGetSymbolAddress((void**)&att_p, g_att);

    const int attn_smem = ATT_SMEM_WORDS * (int)sizeof(uint32_t);
    cudaFuncSetAttribute(attn_mma_kernel, cudaFuncAttributeMaxDynamicSharedMemorySize, attn_smem);

    // 1) QKV = x @ W_qkv : [8192,512] @ [512,1536]  (output tf32-rounded bits)
    tf32_gemm_kernel<<<dim3(QKVN / GBN, ROWS / GBM), 256>>>(x, Wqkv, qkv_p, ROWS, QKVN, DMODEL, 1);

    // 2) tf32 tensor-core attention over the reshaped (flat) layout
    attn_mma_kernel<<<dim3(SEQ / QT, NHEAD, BATCH), 256, attn_smem>>>(
        (const uint32_t*)qkv_p, pmask, att_p);

    // 3) out = att @ W_out : [8192,512] @ [512,512]  (plain fp32 output)
    tf32_gemm_kernel<<<dim3(DMODEL / GBN, ROWS / GBM), 256>>>(att_p, Wout, out, ROWS, DMODEL, DMODEL, 0);
}

// round 14
// speedup vs baseline: 1.6740x; 1.3867x over previous
#include <cuda_runtime.h>
#include <cuda_fp16.h>
#include <math.h>
#include <stdint.h>

#define BATCH   4
#define SEQ     2048
#define DMODEL  512
#define NHEAD   8
#define HDIM    64
#define ROWS    (BATCH * SEQ)        /* 8192 */
#define QKVN    (3 * DMODEL)         /* 1536 */

// Scratch (allocation-free rule: device globals), plain fp32
__device__ float g_qkv[(size_t)ROWS * QKVN];     // [8192, 1536]
__device__ float g_att[(size_t)ROWS * DMODEL];   // [8192, 512]

__device__ __forceinline__ uint32_t f2tf(float x) {
    uint32_t r;
    asm("cvt.rna.tf32.f32 %0, %1;" : "=r"(r) : "f"(x));
    return r;
}

// pack two floats to fp16x2: low half = lo, high half = hi
__device__ __forceinline__ uint32_t h2pk(float lo, float hi) {
    uint32_t r;
    asm("cvt.rn.f16x2.f32 %0, %1, %2;" : "=r"(r) : "f"(hi), "f"(lo));
    return r;
}

__device__ __forceinline__ void mma_tf32(float c[4], const uint32_t a[4],
                                         uint32_t b0, uint32_t b1) {
    asm volatile(
        "mma.sync.aligned.m16n8k8.row.col.f32.tf32.tf32.f32 "
        "{%0,%1,%2,%3}, {%4,%5,%6,%7}, {%8,%9}, {%0,%1,%2,%3};"
        : "+f"(c[0]), "+f"(c[1]), "+f"(c[2]), "+f"(c[3])
        : "r"(a[0]), "r"(a[1]), "r"(a[2]), "r"(a[3]), "r"(b0), "r"(b1));
}

__device__ __forceinline__ void mma_f16(float c[4], const uint32_t a[4],
                                        uint32_t b0, uint32_t b1) {
    asm volatile(
        "mma.sync.aligned.m16n8k16.row.col.f32.f16.f16.f32 "
        "{%0,%1,%2,%3}, {%4,%5,%6,%7}, {%8,%9}, {%0,%1,%2,%3};"
        : "+f"(c[0]), "+f"(c[1]), "+f"(c[2]), "+f"(c[3])
        : "r"(a[0]), "r"(a[1]), "r"(a[2]), "r"(a[3]), "r"(b0), "r"(b1));
}

__device__ __forceinline__ void cp_async16(uint32_t smem_dst, const void* gsrc) {
    asm volatile("cp.async.cg.shared.global [%0], [%1], 16;"
                 :: "r"(smem_dst), "l"(gsrc) : "memory");
}
__device__ __forceinline__ void cp_async_commit() {
    asm volatile("cp.async.commit_group;" ::: "memory");
}
__device__ __forceinline__ void cp_async_wait1() {
    asm volatile("cp.async.wait_group 1;" ::: "memory");
}

// ---------------------------------------------------------------------------
// TF32 tensor-core GEMM, 2-stage cp.async pipeline (exact R9 version).
// ---------------------------------------------------------------------------
#define GBM 128
#define GBN 128
#define GBK 16
#define APAD 20
#define BPAD 136
#define AW (GBM * APAD)
#define BW (GBK * BPAD)

__global__ __launch_bounds__(256)
void tf32_gemm_kernel(const float* __restrict__ A, const float* __restrict__ B,
                      float* __restrict__ C, int M, int N, int K, int cvt_out) {
    __shared__ float As[2][AW];
    __shared__ float Bs[2][BW];

    const int tid  = threadIdx.x;
    const int warp = tid >> 5;
    const int lane = tid & 31;
    const int g = lane >> 2;
    const int c = lane & 3;
    const int wm = warp >> 2;
    const int wn = warp & 3;

    const int arow = tid >> 1, acol = (tid & 1) << 3;
    const int brow = tid >> 4, bcol = (tid & 15) << 3;

    const float* Ag = A + (size_t)(blockIdx.y * GBM + arow) * K + acol;
    const float* Bg = B + (size_t)brow * N + blockIdx.x * GBN + bcol;

    const uint32_t a_dst[2] = {
        (uint32_t)__cvta_generic_to_shared(&As[0][arow * APAD + acol]),
        (uint32_t)__cvta_generic_to_shared(&As[1][arow * APAD + acol]) };
    const uint32_t b_dst[2] = {
        (uint32_t)__cvta_generic_to_shared(&Bs[0][brow * BPAD + bcol]),
        (uint32_t)__cvta_generic_to_shared(&Bs[1][brow * BPAD + bcol]) };

    float acc[4][4][4];
    #pragma unroll
    for (int mf = 0; mf < 4; mf++)
        #pragma unroll
        for (int nf = 0; nf < 4; nf++)
            #pragma unroll
            for (int j = 0; j < 4; j++) acc[mf][nf][j] = 0.f;

    const int nIter = K / GBK;

    cp_async16(a_dst[0],      Ag);
    cp_async16(a_dst[0] + 16, Ag + 4);
    cp_async16(b_dst[0],      Bg);
    cp_async16(b_dst[0] + 16, Bg + 4);
    cp_async_commit();

    for (int it = 0; it < nIter; it++) {
        const int cur = it & 1, nxt = cur ^ 1;

        if (it + 1 < nIter) {
            const int k0 = (it + 1) * GBK;
            cp_async16(a_dst[nxt],      Ag + k0);
            cp_async16(a_dst[nxt] + 16, Ag + k0 + 4);
            cp_async16(b_dst[nxt],      Bg + (size_t)k0 * N);
            cp_async16(b_dst[nxt] + 16, Bg + (size_t)k0 * N + 4);
        }
        cp_async_commit();
        cp_async_wait1();
        __syncthreads();

        const float* Asc = As[cur];
        const float* Bsc = Bs[cur];

        #pragma unroll
        for (int kk = 0; kk < GBK; kk += 8) {
            uint32_t af[4][4], bf0[4], bf1[4];
            #pragma unroll
            for (int mf = 0; mf < 4; mf++) {
                const int r0 = wm * 64 + mf * 16 + g;
                af[mf][0] = f2tf(Asc[(r0    ) * APAD + kk + c    ]);
                af[mf][1] = f2tf(Asc[(r0 + 8) * APAD + kk + c    ]);
                af[mf][2] = f2tf(Asc[(r0    ) * APAD + kk + c + 4]);
                af[mf][3] = f2tf(Asc[(r0 + 8) * APAD + kk + c + 4]);
            }
            #pragma unroll
            for (int nf = 0; nf < 4; nf++) {
                const int n = wn * 32 + nf * 8 + g;
                bf0[nf] = f2tf(Bsc[(kk + c    ) * BPAD + n]);
                bf1[nf] = f2tf(Bsc[(kk + c + 4) * BPAD + n]);
            }
            #pragma unroll
            for (int mf = 0; mf < 4; mf++)
                #pragma unroll
                for (int nf = 0; nf < 4; nf++)
                    mma_tf32(acc[mf][nf], af[mf], bf0[nf], bf1[nf]);
        }
        __syncthreads();
    }

    #pragma unroll
    for (int mf = 0; mf < 4; mf++) {
        const int r0 = blockIdx.y * GBM + wm * 64 + mf * 16 + g;
        #pragma unroll
        for (int nf = 0; nf < 4; nf++) {
            const int col = blockIdx.x * GBN + wn * 32 + nf * 8 + 2 * c;
            float v0 = acc[mf][nf][0], v1 = acc[mf][nf][1];
            float v2 = acc[mf][nf][2], v3 = acc[mf][nf][3];
            if (cvt_out) {
                v0 = __uint_as_float(f2tf(v0)); v1 = __uint_as_float(f2tf(v1));
                v2 = __uint_as_float(f2tf(v2)); v3 = __uint_as_float(f2tf(v3));
            }
            *(float2*)&C[(size_t)r0 * N + col]       = make_float2(v0, v1);
            *(float2*)&C[(size_t)(r0 + 8) * N + col] = make_float2(v2, v3);
        }
    }
}

// ---------------------------------------------------------------------------
// FP16 tensor-core flash attention (m16n8k16, fp32 accumulate).
// Block = 256 threads (8 warps), 128 queries of one (b,h'); streams 64-key
// tiles. Q/K stored as fp16x2 packed along dims; V stored TRANSPOSED as
// Vt[dim][keypair] so PV B-frags are direct LDS. P never touches smem:
// S-fragment layout == A-fragment layout for m16n8k16 (cvt in registers).
// ---------------------------------------------------------------------------
#define QP 36
#define KP 36
#define VP 36
#define QT 128

__global__ __launch_bounds__(256)
void attn_mma_kernel(const float* __restrict__ qkv, const int* __restrict__ pmask,
                     float* __restrict__ attout) {
    __shared__ uint32_t Qs[128 * QP];   // fp16x2, dims packed
    __shared__ uint32_t Ks[64 * KP];    // fp16x2, dims packed
    __shared__ uint32_t Vt[64 * VP];    // fp16x2, [dim][keypair]
    __shared__ float    mk[64];

    const int qt = blockIdx.x, h = blockIdx.y, b = blockIdx.z;
    const int tid  = threadIdx.x;
    const int warp = tid >> 5;
    const int lane = tid & 31;
    const int g = lane >> 2;
    const int c = lane & 3;

    const size_t rbase = (size_t)b * (NHEAD * SEQ) + (size_t)h * SEQ;
    const float* qkv_b = qkv + rbase * (3 * HDIM);

    // Q loader: 2 thr/row, 32 fp32 each -> 16 fp16x2 words
    const int qrow = tid >> 1;
    const int qsel = tid & 1;
    // KV loader: 4 thr/row, 16 fp32 each
    const int lrow = tid >> 2;
    const int fsel = tid & 3;

    // ---- stage Q tile (fp32 -> fp16x2) ----
    {
        const float4* src = (const float4*)(qkv_b + (size_t)(qt * QT + qrow) * (3 * HDIM) + qsel * 32);
        uint32_t* dst = &Qs[qrow * QP + qsel * 16];
        #pragma unroll
        for (int u = 0; u < 8; u++) {
            float4 v = src[u];
            dst[2*u]   = h2pk(v.x, v.y);
            dst[2*u+1] = h2pk(v.z, v.w);
        }
    }
    __syncthreads();

    // ---- Q fragments: qa[ch] covers dims ch*16..ch*16+15 ----
    uint32_t qa[4][4];
    {
        const int r0 = warp * 16 + g;
        #pragma unroll
        for (int ch = 0; ch < 4; ch++) {
            qa[ch][0] = Qs[(r0    ) * QP + ch * 8 + c    ];
            qa[ch][1] = Qs[(r0 + 8) * QP + ch * 8 + c    ];
            qa[ch][2] = Qs[(r0    ) * QP + ch * 8 + c + 4];
            qa[ch][3] = Qs[(r0 + 8) * QP + ch * 8 + c + 4];
        }
    }

    float o[8][4];
    #pragma unroll
    for (int nf = 0; nf < 8; nf++)
        #pragma unroll
        for (int j = 0; j < 4; j++) o[nf][j] = 0.f;
    float m0 = -INFINITY, m1 = -INFINITY, l0 = 0.f, l1 = 0.f;

    for (int kt = 0; kt < SEQ / 64; kt++) {
        __syncthreads();   // prior-iteration reads of Ks/Vt/mk complete

        // ---- stage K (packed along dims) ----
        {
            const float4* srck = (const float4*)(qkv_b + (size_t)(kt * 64 + lrow) * (3 * HDIM) + HDIM + fsel * 16);
            uint32_t* dk = &Ks[lrow * KP + fsel * 8];
            #pragma unroll
            for (int u = 0; u < 4; u++) {
                float4 v = srck[u];
                dk[2*u]   = h2pk(v.x, v.y);
                dk[2*u+1] = h2pk(v.z, v.w);
            }
        }
        // ---- stage V transposed: Vt[dim][keypair], 16-bit scatter ----
        {
            const float4* srcv = (const float4*)(qkv_b + (size_t)(kt * 64 + lrow) * (3 * HDIM) + 2 * HDIM + fsel * 16);
            __half* hv = (__half*)Vt;
            const int kp = lrow >> 1, kh = lrow & 1;
            #pragma unroll
            for (int u = 0; u < 4; u++) {
                float4 v = srcv[u];
                const int d = fsel * 16 + 4 * u;
                hv[(size_t)((d    ) * VP + kp) * 2 + kh] = __float2half_rn(v.x);
                hv[(size_t)((d + 1) * VP + kp) * 2 + kh] = __float2half_rn(v.y);
                hv[(size_t)((d + 2) * VP + kp) * 2 + kh] = __float2half_rn(v.z);
                hv[(size_t)((d + 3) * VP + kp) * 2 + kh] = __float2half_rn(v.w);
            }
            if (tid < 64)
                mk[tid] = (pmask[b * SEQ + kt * 64 + tid] != 0) ? 0.f : -INFINITY;
        }
        __syncthreads();

        // ---- S = Q K^T  (8 key-groups x 4 dim-chunks) ----
        float s[8][4];
        #pragma unroll
        for (int kg = 0; kg < 8; kg++) {
            s[kg][0] = s[kg][1] = s[kg][2] = s[kg][3] = 0.f;
            const uint32_t* kbase = &Ks[(kg * 8 + g) * KP + c];
            #pragma unroll
            for (int ch = 0; ch < 4; ch++)
                mma_f16(s[kg], qa[ch], kbase[ch * 8], kbase[ch * 8 + 4]);
        }

        // ---- scale + mask ----
        #pragma unroll
        for (int kg = 0; kg < 8; kg++) {
            const int col0 = kg * 8 + 2 * c;
            float mk0 = mk[col0], mk1 = mk[col0 + 1];
            s[kg][0] = s[kg][0] * 0.125f + mk0;
            s[kg][1] = s[kg][1] * 0.125f + mk1;
            s[kg][2] = s[kg][2] * 0.125f + mk0;
            s[kg][3] = s[kg][3] * 0.125f + mk1;
        }

        // ---- online softmax ----
        float mx0 = -INFINITY, mx1 = -INFINITY;
        #pragma unroll
        for (int kg = 0; kg < 8; kg++) {
            mx0 = fmaxf(mx0, fmaxf(s[kg][0], s[kg][1]));
            mx1 = fmaxf(mx1, fmaxf(s[kg][2], s[kg][3]));
        }
        mx0 = fmaxf(mx0, __shfl_xor_sync(0xffffffffu, mx0, 1));
        mx0 = fmaxf(mx0, __shfl_xor_sync(0xffffffffu, mx0, 2));
        mx1 = fmaxf(mx1, __shfl_xor_sync(0xffffffffu, mx1, 1));
        mx1 = fmaxf(mx1, __shfl_xor_sync(0xffffffffu, mx1, 2));

        float mn0 = fmaxf(m0, mx0), mn1 = fmaxf(m1, mx1);
        float sc0 = (mn0 == -INFINITY) ? 1.f : __expf(m0 - mn0);
        float sc1 = (mn1 == -INFINITY) ? 1.f : __expf(m1 - mn1);

        // ---- P in registers: exp, sum, convert straight to A-fragments ----
        float sum0 = 0.f, sum1 = 0.f;
        uint32_t pa[4][4];
        #pragma unroll
        for (int ch = 0; ch < 4; ch++) {
            const int ke = 2 * ch, ko = 2 * ch + 1;
            float e0 = (s[ke][0] == -INFINITY) ? 0.f : __expf(s[ke][0] - mn0);
            float e1 = (s[ke][1] == -INFINITY) ? 0.f : __expf(s[ke][1] - mn0);
            float e2 = (s[ke][2] == -INFINITY) ? 0.f : __expf(s[ke][2] - mn1);
            float e3 = (s[ke][3] == -INFINITY) ? 0.f : __expf(s[ke][3] - mn1);
            float o0 = (s[ko][0] == -INFINITY) ? 0.f : __expf(s[ko][0] - mn0);
            float o1 = (s[ko][1] == -INFINITY) ? 0.f : __expf(s[ko][1] - mn0);
            float o2 = (s[ko][2] == -INFINITY) ? 0.f : __expf(s[ko][2] - mn1);
            float o3 = (s[ko][3] == -INFINITY) ? 0.f : __expf(s[ko][3] - mn1);
            sum0 += e0 + e1 + o0 + o1;
            sum1 += e2 + e3 + o2 + o3;
            pa[ch][0] = h2pk(e0, e1);   // row g,   keys ch*16+2c,2c+1
            pa[ch][1] = h2pk(e2, e3);   // row g+8, keys ch*16+2c,2c+1
            pa[ch][2] = h2pk(o0, o1);   // row g,   keys ch*16+8+2c,..
            pa[ch][3] = h2pk(o2, o3);   // row g+8
        }
        sum0 += __shfl_xor_sync(0xffffffffu, sum0, 1);
        sum0 += __shfl_xor_sync(0xffffffffu, sum0, 2);
        sum1 += __shfl_xor_sync(0xffffffffu, sum1, 1);
        sum1 += __shfl_xor_sync(0xffffffffu, sum1, 2);

        l0 = l0 * sc0 + sum0;  m0 = mn0;
        l1 = l1 * sc1 + sum1;  m1 = mn1;

        #pragma unroll
        for (int nf = 0; nf < 8; nf++) {
            o[nf][0] *= sc0; o[nf][1] *= sc0;
            o[nf][2] *= sc1; o[nf][3] *= sc1;
        }

        // ---- O += P V  (B-frags from transposed Vt, direct LDS) ----
        #pragma unroll
        for (int ch = 0; ch < 4; ch++) {
            const uint32_t* vb = &Vt[g * VP + ch * 8 + c];
            #pragma unroll
            for (int nf = 0; nf < 8; nf++)
                mma_f16(o[nf], pa[ch], vb[nf * 8 * VP], vb[nf * 8 * VP + 4]);
        }
    }

    // ---- epilogue ----
    {
        const int r0 = warp * 16 + g;
        const int row0 = qt * QT + r0, row1 = row0 + 8;
        float inv0 = (l0 > 0.f) ? (1.f / l0) : 0.f;
        float inv1 = (l1 > 0.f) ? (1.f / l1) : 0.f;
        if (pmask[b * SEQ + row0] == 0) inv0 = 0.f;
        if (pmask[b * SEQ + row1] == 0) inv1 = 0.f;
        float* out0 = attout + (rbase + row0) * HDIM + 2 * c;
        float* out1 = attout + (rbase + row1) * HDIM + 2 * c;
        #pragma unroll
        for (int nf = 0; nf < 8; nf++) {
            *(float2*)(out0 + nf * 8) = make_float2(o[nf][0] * inv0, o[nf][1] * inv0);
            *(float2*)(out1 + nf * 8) = make_float2(o[nf][2] * inv1, o[nf][3] * inv1);
        }
    }
}

// ---------------------------------------------------------------------------
extern "C" void kernel_launch(void* const* d_in, const int* in_sizes, int n_in,
                              void* d_out, int out_size) {
    const float* x     = (const float*)d_in[0];
    const int*   pmask = (const int*)d_in[2];
    const float* Wqkv  = (const float*)d_in[3];
    const float* Wout  = (const float*)d_in[4];
    float* out = (float*)d_out;

    float *qkv_p = nullptr, *att_p = nullptr;
    cudaGetSymbolAddress((void**)&qkv_p, g_qkv);
    cudaGetSymbolAddress((void**)&att_p, g_att);

    // 1) QKV = x @ W_qkv : [8192,512] @ [512,1536]  (plain fp32 out)
    tf32_gemm_kernel<<<dim3(QKVN / GBN, ROWS / GBM), 256>>>(x, Wqkv, qkv_p, ROWS, QKVN, DMODEL, 0);

    // 2) fp16 tensor-core attention over the reshaped (flat) layout
    attn_mma_kernel<<<dim3(SEQ / QT, NHEAD, BATCH), 256>>>(qkv_p, pmask, att_p);

    // 3) out = att @ W_out : [8192,512] @ [512,512]  (plain fp32 out)
    tf32_gemm_kernel<<<dim3(DMODEL / GBN, ROWS / GBM), 256>>>(att_p, Wout, out, ROWS, DMODEL, DMODEL, 0);
}

// round 15
// speedup vs baseline: 2.2452x; 1.3412x over previous
#include <cuda_runtime.h>
#include <cuda_fp16.h>
#include <math.h>
#include <stdint.h>

#define BATCH   4
#define SEQ     2048
#define DMODEL  512
#define NHEAD   8
#define HDIM    64
#define ROWS    (BATCH * SEQ)        /* 8192 */
#define QKVN    (3 * DMODEL)         /* 1536 */

// Scratch (allocation-free rule: device globals). fp16x2 word buffers.
__device__ uint32_t g_qkvh[(size_t)ROWS * (QKVN / 2)];    // [8192][768 words]
__device__ uint32_t g_atth[(size_t)ROWS * (DMODEL / 2)];  // [8192][256 words]
__device__ uint32_t g_xh  [(size_t)ROWS * (DMODEL / 2)];  // x as fp16 words
__device__ uint32_t g_wqt [(size_t)QKVN * (DMODEL / 2)];  // Wqkv^T [1536][256w]
__device__ uint32_t g_wot [(size_t)DMODEL * (DMODEL / 2)];// Wout^T [512][256w]

// pack two floats to fp16x2: low half = lo, high half = hi
__device__ __forceinline__ uint32_t h2pk(float lo, float hi) {
    uint32_t r;
    asm("cvt.rn.f16x2.f32 %0, %1, %2;" : "=r"(r) : "f"(hi), "f"(lo));
    return r;
}

__device__ __forceinline__ void mma_f16(float c[4], const uint32_t a[4],
                                        uint32_t b0, uint32_t b1) {
    asm volatile(
        "mma.sync.aligned.m16n8k16.row.col.f32.f16.f16.f32 "
        "{%0,%1,%2,%3}, {%4,%5,%6,%7}, {%8,%9}, {%0,%1,%2,%3};"
        : "+f"(c[0]), "+f"(c[1]), "+f"(c[2]), "+f"(c[3])
        : "r"(a[0]), "r"(a[1]), "r"(a[2]), "r"(a[3]), "r"(b0), "r"(b1));
}

__device__ __forceinline__ void cp_async16(uint32_t smem_dst, const void* gsrc) {
    asm volatile("cp.async.cg.shared.global [%0], [%1], 16;"
                 :: "r"(smem_dst), "l"(gsrc) : "memory");
}
__device__ __forceinline__ void cp_async_commit() {
    asm volatile("cp.async.commit_group;" ::: "memory");
}
__device__ __forceinline__ void cp_async_wait1() {
    asm volatile("cp.async.wait_group 1;" ::: "memory");
}

// ---------------------------------------------------------------------------
// Pre-pass 1: x (fp32, [8192][512]) -> g_xh fp16x2 words (packed along k).
// ---------------------------------------------------------------------------
__global__ __launch_bounds__(256)
void convert_x_kernel(const float4* __restrict__ x) {
    const int n4 = (ROWS * DMODEL) / 4;
    for (int i = blockIdx.x * blockDim.x + threadIdx.x; i < n4;
         i += gridDim.x * blockDim.x) {
        float4 v = x[i];
        g_xh[2 * i]     = h2pk(v.x, v.y);
        g_xh[2 * i + 1] = h2pk(v.z, v.w);
    }
}

// ---------------------------------------------------------------------------
// Pre-pass 2: W [K][N] fp32 -> Wt fp16x2 words [N][K/2] (packed along k).
// 32x32 tiles via smem.
// ---------------------------------------------------------------------------
__global__ __launch_bounds__(256)
void transpose_w_kernel(const float* __restrict__ W, uint32_t* __restrict__ Wt,
                        int K, int N) {
    __shared__ float tile[32][33];
    const int n0 = blockIdx.x * 32, k0 = blockIdx.y * 32;
    const int t = threadIdx.x;
    const int ln = t & 31, lk4 = (t >> 5) * 4;
    #pragma unroll
    for (int j = 0; j < 4; j++)
        tile[lk4 + j][ln] = W[(size_t)(k0 + lk4 + j) * N + n0 + ln];
    __syncthreads();
    const int Kw = K / 2;
    #pragma unroll
    for (int j = 0; j < 2; j++) {
        const int w = t * 2 + j;           // 0..511
        const int n = w >> 4, kw = w & 15; // 32 n x 16 words
        Wt[(size_t)(n0 + n) * Kw + (k0 >> 1) + kw] =
            h2pk(tile[2 * kw][n], tile[2 * kw + 1][n]);
    }
}

// ---------------------------------------------------------------------------
// FP16 tensor-core GEMM, 2-stage cp.async pipeline.
// C[M,N] = A[M,K] @ B[K,N] with A as fp16x2 words [M][Kw] (packed along k)
// and B pre-transposed fp16x2 words Bt[N][Kw]. 128x128 block tile, k=32 per
// iteration (2 chunks of k16), 8 warps (2x4), 64x32 warp tile.
// out_fp16: C stored as fp16x2 words [M][N/2]; else fp32.
// ---------------------------------------------------------------------------
#define HPAD 20
#define HW (128 * HPAD)

__global__ __launch_bounds__(256)
void h16_gemm_kernel(const uint32_t* __restrict__ A, const uint32_t* __restrict__ Bt,
                     void* __restrict__ C, int M, int N, int Kw, int out_fp16) {
    __shared__ uint32_t As[2][HW];
    __shared__ uint32_t Bs[2][HW];

    const int tid  = threadIdx.x;
    const int warp = tid >> 5;
    const int lane = tid & 31;
    const int g = lane >> 2;
    const int c = lane & 3;
    const int wm = warp >> 2;     // 0..1
    const int wn = warp & 3;      // 0..3

    // loaders: 128 rows x 16 words per tile; 2 thr/row, 8 words each
    const int lrow = tid >> 1, lcol = (tid & 1) << 3;

    const uint32_t* Ag = A  + (size_t)(blockIdx.y * 128 + lrow) * Kw + lcol;
    const uint32_t* Bg = Bt + (size_t)(blockIdx.x * 128 + lrow) * Kw + lcol;

    const uint32_t a_dst[2] = {
        (uint32_t)__cvta_generic_to_shared(&As[0][lrow * HPAD + lcol]),
        (uint32_t)__cvta_generic_to_shared(&As[1][lrow * HPAD + lcol]) };
    const uint32_t b_dst[2] = {
        (uint32_t)__cvta_generic_to_shared(&Bs[0][lrow * HPAD + lcol]),
        (uint32_t)__cvta_generic_to_shared(&Bs[1][lrow * HPAD + lcol]) };

    float acc[4][4][4];
    #pragma unroll
    for (int mf = 0; mf < 4; mf++)
        #pragma unroll
        for (int nf = 0; nf < 4; nf++)
            #pragma unroll
            for (int j = 0; j < 4; j++) acc[mf][nf][j] = 0.f;

    const int nIter = Kw / 16;

    cp_async16(a_dst[0],      Ag);
    cp_async16(a_dst[0] + 16, Ag + 4);
    cp_async16(b_dst[0],      Bg);
    cp_async16(b_dst[0] + 16, Bg + 4);
    cp_async_commit();

    for (int it = 0; it < nIter; it++) {
        const int cur = it & 1, nxt = cur ^ 1;

        if (it + 1 < nIter) {
            const int k0 = (it + 1) * 16;
            cp_async16(a_dst[nxt],      Ag + k0);
            cp_async16(a_dst[nxt] + 16, Ag + k0 + 4);
            cp_async16(b_dst[nxt],      Bg + k0);
            cp_async16(b_dst[nxt] + 16, Bg + k0 + 4);
        }
        cp_async_commit();
        cp_async_wait1();
        __syncthreads();

        const uint32_t* Asc = As[cur];
        const uint32_t* Bsc = Bs[cur];

        #pragma unroll
        for (int ch = 0; ch < 2; ch++) {
            uint32_t af[4][4], bf0[4], bf1[4];
            #pragma unroll
            for (int mf = 0; mf < 4; mf++) {
                const int r0 = wm * 64 + mf * 16 + g;
                af[mf][0] = Asc[(r0    ) * HPAD + ch * 8 + c    ];
                af[mf][1] = Asc[(r0 + 8) * HPAD + ch * 8 + c    ];
                af[mf][2] = Asc[(r0    ) * HPAD + ch * 8 + c + 4];
                af[mf][3] = Asc[(r0 + 8) * HPAD + ch * 8 + c + 4];
            }
            #pragma unroll
            for (int nf = 0; nf < 4; nf++) {
                const int n = wn * 32 + nf * 8 + g;
                bf0[nf] = Bsc[n * HPAD + ch * 8 + c    ];
                bf1[nf] = Bsc[n * HPAD + ch * 8 + c + 4];
            }
            #pragma unroll
            for (int mf = 0; mf < 4; mf++)
                #pragma unroll
                for (int nf = 0; nf < 4; nf++)
                    mma_f16(acc[mf][nf], af[mf], bf0[nf], bf1[nf]);
        }
        __syncthreads();
    }

    // ---- epilogue ----
    #pragma unroll
    for (int mf = 0; mf < 4; mf++) {
        const int r0 = blockIdx.y * 128 + wm * 64 + mf * 16 + g;
        #pragma unroll
        for (int nf = 0; nf < 4; nf++) {
            if (out_fp16) {
                uint32_t* Cw = (uint32_t*)C;
                const int wcol = blockIdx.x * 64 + wn * 16 + nf * 4 + c;
                Cw[(size_t)r0 * (N / 2) + wcol] =
                    h2pk(acc[mf][nf][0], acc[mf][nf][1]);
                Cw[(size_t)(r0 + 8) * (N / 2) + wcol] =
                    h2pk(acc[mf][nf][2], acc[mf][nf][3]);
            } else {
                float* Cf = (float*)C;
                const int col = blockIdx.x * 128 + wn * 32 + nf * 8 + 2 * c;
                *(float2*)&Cf[(size_t)r0 * N + col] =
                    make_float2(acc[mf][nf][0], acc[mf][nf][1]);
                *(float2*)&Cf[(size_t)(r0 + 8) * N + col] =
                    make_float2(acc[mf][nf][2], acc[mf][nf][3]);
            }
        }
    }
}

// ---------------------------------------------------------------------------
// FP16 flash attention (R14 structure; input qkv already fp16x2 words).
// Block = 256 threads (8 warps), 128 queries of one (b,h'); 64-key tiles.
// qkv row = 96 words: Q 0..31, K 32..63, V 64..95. Staging is pure copy
// except the V transpose scatter. P stays in registers. Output fp16 words.
// ---------------------------------------------------------------------------
#define QP 36
#define KP 36
#define VP 36
#define QT 128

__global__ __launch_bounds__(256)
void attn_mma_kernel(const uint32_t* __restrict__ qkv, const int* __restrict__ pmask,
                     uint32_t* __restrict__ attout) {
    __shared__ uint32_t Qs[128 * QP];
    __shared__ uint32_t Ks[64 * KP];
    __shared__ uint32_t Vt[64 * VP];
    __shared__ float    mk[64];

    const int qt = blockIdx.x, h = blockIdx.y, b = blockIdx.z;
    const int tid  = threadIdx.x;
    const int warp = tid >> 5;
    const int lane = tid & 31;
    const int g = lane >> 2;
    const int c = lane & 3;

    const size_t rbase = (size_t)b * (NHEAD * SEQ) + (size_t)h * SEQ;
    const uint32_t* qkv_b = qkv + rbase * 96;

    const int qrow = tid >> 1, qsel = tid & 1;
    const int lrow = tid >> 2, fsel = tid & 3;

    // ---- stage Q tile (pure word copy) ----
    {
        const uint4* src = (const uint4*)(qkv_b + (size_t)(qt * QT + qrow) * 96 + qsel * 16);
        uint4* dst = (uint4*)&Qs[qrow * QP + qsel * 16];
        #pragma unroll
        for (int u = 0; u < 4; u++) dst[u] = src[u];
    }
    __syncthreads();

    // ---- Q fragments ----
    uint32_t qa[4][4];
    {
        const int r0 = warp * 16 + g;
        #pragma unroll
        for (int ch = 0; ch < 4; ch++) {
            qa[ch][0] = Qs[(r0    ) * QP + ch * 8 + c    ];
            qa[ch][1] = Qs[(r0 + 8) * QP + ch * 8 + c    ];
            qa[ch][2] = Qs[(r0    ) * QP + ch * 8 + c + 4];
            qa[ch][3] = Qs[(r0 + 8) * QP + ch * 8 + c + 4];
        }
    }

    float o[8][4];
    #pragma unroll
    for (int nf = 0; nf < 8; nf++)
        #pragma unroll
        for (int j = 0; j < 4; j++) o[nf][j] = 0.f;
    float m0 = -INFINITY, m1 = -INFINITY, l0 = 0.f, l1 = 0.f;

    for (int kt = 0; kt < SEQ / 64; kt++) {
        __syncthreads();

        // ---- stage K (pure copy) + V (transpose scatter) + mask ----
        {
            const uint32_t* row = qkv_b + (size_t)(kt * 64 + lrow) * 96;
            const uint4* srck = (const uint4*)(row + 32 + fsel * 8);
            uint4* dk = (uint4*)&Ks[lrow * KP + fsel * 8];
            dk[0] = srck[0]; dk[1] = srck[1];

            const uint4* srcv = (const uint4*)(row + 64 + fsel * 8);
            uint4 v0 = srcv[0], v1 = srcv[1];
            const uint32_t vw[8] = { v0.x, v0.y, v0.z, v0.w, v1.x, v1.y, v1.z, v1.w };
            __half* hv = (__half*)Vt;
            const int kp = lrow >> 1, kh = lrow & 1;
            #pragma unroll
            for (int u = 0; u < 8; u++) {
                const __half2 hw = *(const __half2*)&vw[u];
                const int d = fsel * 16 + 2 * u;
                hv[(size_t)((d    ) * VP + kp) * 2 + kh] = __low2half(hw);
                hv[(size_t)((d + 1) * VP + kp) * 2 + kh] = __high2half(hw);
            }
            if (tid < 64)
                mk[tid] = (pmask[b * SEQ + kt * 64 + tid] != 0) ? 0.f : -INFINITY;
        }
        __syncthreads();

        // ---- S = Q K^T ----
        float s[8][4];
        #pragma unroll
        for (int kg = 0; kg < 8; kg++) {
            s[kg][0] = s[kg][1] = s[kg][2] = s[kg][3] = 0.f;
            const uint32_t* kbase = &Ks[(kg * 8 + g) * KP + c];
            #pragma unroll
            for (int ch = 0; ch < 4; ch++)
                mma_f16(s[kg], qa[ch], kbase[ch * 8], kbase[ch * 8 + 4]);
        }

        // ---- scale + mask ----
        #pragma unroll
        for (int kg = 0; kg < 8; kg++) {
            const int col0 = kg * 8 + 2 * c;
            float mk0 = mk[col0], mk1 = mk[col0 + 1];
            s[kg][0] = s[kg][0] * 0.125f + mk0;
            s[kg][1] = s[kg][1] * 0.125f + mk1;
            s[kg][2] = s[kg][2] * 0.125f + mk0;
            s[kg][3] = s[kg][3] * 0.125f + mk1;
        }

        // ---- online softmax ----
        float mx0 = -INFINITY, mx1 = -INFINITY;
        #pragma unroll
        for (int kg = 0; kg < 8; kg++) {
            mx0 = fmaxf(mx0, fmaxf(s[kg][0], s[kg][1]));
            mx1 = fmaxf(mx1, fmaxf(s[kg][2], s[kg][3]));
        }
        mx0 = fmaxf(mx0, __shfl_xor_sync(0xffffffffu, mx0, 1));
        mx0 = fmaxf(mx0, __shfl_xor_sync(0xffffffffu, mx0, 2));
        mx1 = fmaxf(mx1, __shfl_xor_sync(0xffffffffu, mx1, 1));
        mx1 = fmaxf(mx1, __shfl_xor_sync(0xffffffffu, mx1, 2));

        float mn0 = fmaxf(m0, mx0), mn1 = fmaxf(m1, mx1);
        float sc0 = (mn0 == -INFINITY) ? 1.f : __expf(m0 - mn0);
        float sc1 = (mn1 == -INFINITY) ? 1.f : __expf(m1 - mn1);

        // ---- P in registers ----
        float sum0 = 0.f, sum1 = 0.f;
        uint32_t pa[4][4];
        #pragma unroll
        for (int ch = 0; ch < 4; ch++) {
            const int ke = 2 * ch, ko = 2 * ch + 1;
            float e0 = (s[ke][0] == -INFINITY) ? 0.f : __expf(s[ke][0] - mn0);
            float e1 = (s[ke][1] == -INFINITY) ? 0.f : __expf(s[ke][1] - mn0);
            float e2 = (s[ke][2] == -INFINITY) ? 0.f : __expf(s[ke][2] - mn1);
            float e3 = (s[ke][3] == -INFINITY) ? 0.f : __expf(s[ke][3] - mn1);
            float o0 = (s[ko][0] == -INFINITY) ? 0.f : __expf(s[ko][0] - mn0);
            float o1 = (s[ko][1] == -INFINITY) ? 0.f : __expf(s[ko][1] - mn0);
            float o2 = (s[ko][2] == -INFINITY) ? 0.f : __expf(s[ko][2] - mn1);
            float o3 = (s[ko][3] == -INFINITY) ? 0.f : __expf(s[ko][3] - mn1);
            sum0 += e0 + e1 + o0 + o1;
            sum1 += e2 + e3 + o2 + o3;
            pa[ch][0] = h2pk(e0, e1);
            pa[ch][1] = h2pk(e2, e3);
            pa[ch][2] = h2pk(o0, o1);
            pa[ch][3] = h2pk(o2, o3);
        }
        sum0 += __shfl_xor_sync(0xffffffffu, sum0, 1);
        sum0 += __shfl_xor_sync(0xffffffffu, sum0, 2);
        sum1 += __shfl_xor_sync(0xffffffffu, sum1, 1);
        sum1 += __shfl_xor_sync(0xffffffffu, sum1, 2);

        l0 = l0 * sc0 + sum0;  m0 = mn0;
        l1 = l1 * sc1 + sum1;  m1 = mn1;

        #pragma unroll
        for (int nf = 0; nf < 8; nf++) {
            o[nf][0] *= sc0; o[nf][1] *= sc0;
            o[nf][2] *= sc1; o[nf][3] *= sc1;
        }

        // ---- O += P V ----
        #pragma unroll
        for (int ch = 0; ch < 4; ch++) {
            const uint32_t* vb = &Vt[g * VP + ch * 8 + c];
            #pragma unroll
            for (int nf = 0; nf < 8; nf++)
                mma_f16(o[nf], pa[ch], vb[nf * 8 * VP], vb[nf * 8 * VP + 4]);
        }
    }

    // ---- epilogue: normalize, validity, store fp16 words ----
    {
        const int r0 = warp * 16 + g;
        const int row0 = qt * QT + r0, row1 = row0 + 8;
        float inv0 = (l0 > 0.f) ? (1.f / l0) : 0.f;
        float inv1 = (l1 > 0.f) ? (1.f / l1) : 0.f;
        if (pmask[b * SEQ + row0] == 0) inv0 = 0.f;
        if (pmask[b * SEQ + row1] == 0) inv1 = 0.f;
        uint32_t* out0 = attout + (rbase + row0) * (HDIM / 2) + c;
        uint32_t* out1 = attout + (rbase + row1) * (HDIM / 2) + c;
        #pragma unroll
        for (int nf = 0; nf < 8; nf++) {
            out0[nf * 4] = h2pk(o[nf][0] * inv0, o[nf][1] * inv0);
            out1[nf * 4] = h2pk(o[nf][2] * inv1, o[nf][3] * inv1);
        }
    }
}

// ---------------------------------------------------------------------------
extern "C" void kernel_launch(void* const* d_in, const int* in_sizes, int n_in,
                              void* d_out, int out_size) {
    const float* x     = (const float*)d_in[0];
    const int*   pmask = (const int*)d_in[2];
    const float* Wqkv  = (const float*)d_in[3];
    const float* Wout  = (const float*)d_in[4];
    float* out = (float*)d_out;

    uint32_t *qkvh_p, *atth_p, *xh_p, *wqt_p, *wot_p;
    cudaGetSymbolAddress((void**)&qkvh_p, g_qkvh);
    cudaGetSymbolAddress((void**)&atth_p, g_atth);
    cudaGetSymbolAddress((void**)&xh_p,   g_xh);
    cudaGetSymbolAddress((void**)&wqt_p,  g_wqt);
    cudaGetSymbolAddress((void**)&wot_p,  g_wot);

    // 0) pre-pass: x -> fp16; Wqkv, Wout -> transposed fp16
    convert_x_kernel<<<2048, 256>>>((const float4*)x);
    transpose_w_kernel<<<dim3(QKVN / 32, DMODEL / 32), 256>>>(Wqkv, wqt_p, DMODEL, QKVN);
    transpose_w_kernel<<<dim3(DMODEL / 32, DMODEL / 32), 256>>>(Wout, wot_p, DMODEL, DMODEL);

    // 1) QKV = x @ W_qkv (fp16 in/out): [8192,512] @ [512,1536]
    h16_gemm_kernel<<<dim3(QKVN / 128, ROWS / 128), 256>>>(
        xh_p, wqt_p, qkvh_p, ROWS, QKVN, DMODEL / 2, 1);

    // 2) fp16 attention over the reshaped (flat) layout
    attn_mma_kernel<<<dim3(SEQ / QT, NHEAD, BATCH), 256>>>(qkvh_p, pmask, atth_p);

    // 3) out = att @ W_out (fp32 out): [8192,512] @ [512,512]
    h16_gemm_kernel<<<dim3(DMODEL / 128, ROWS / 128), 256>>>(
        atth_p, wot_p, out, ROWS, DMODEL, DMODEL / 2, 0);
}

// round 16
// speedup vs baseline: 2.4652x; 1.0980x over previous
#include <cuda_runtime.h>
#include <cuda_fp16.h>
#include <math.h>
#include <stdint.h>

#define BATCH   4
#define SEQ     2048
#define DMODEL  512
#define NHEAD   8
#define HDIM    64
#define ROWS    (BATCH * SEQ)        /* 8192 */
#define QKVN    (3 * DMODEL)         /* 1536 */

// Scratch (allocation-free rule: device globals). fp16x2 word buffers.
__device__ uint32_t g_qkvh[(size_t)ROWS * (QKVN / 2)];    // [8192][768 words]
__device__ uint32_t g_atth[(size_t)ROWS * (DMODEL / 2)];  // [8192][256 words]
__device__ uint32_t g_xh  [(size_t)ROWS * (DMODEL / 2)];  // x as fp16 words
__device__ uint32_t g_wqt [(size_t)QKVN * (DMODEL / 2)];  // Wqkv^T [1536][256w]
__device__ uint32_t g_wot [(size_t)DMODEL * (DMODEL / 2)];// Wout^T [512][256w]

// pack two floats to fp16x2: low half = lo, high half = hi
__device__ __forceinline__ uint32_t h2pk(float lo, float hi) {
    uint32_t r;
    asm("cvt.rn.f16x2.f32 %0, %1, %2;" : "=r"(r) : "f"(hi), "f"(lo));
    return r;
}

__device__ __forceinline__ void mma_f16(float c[4], const uint32_t a[4],
                                        uint32_t b0, uint32_t b1) {
    asm volatile(
        "mma.sync.aligned.m16n8k16.row.col.f32.f16.f16.f32 "
        "{%0,%1,%2,%3}, {%4,%5,%6,%7}, {%8,%9}, {%0,%1,%2,%3};"
        : "+f"(c[0]), "+f"(c[1]), "+f"(c[2]), "+f"(c[3])
        : "r"(a[0]), "r"(a[1]), "r"(a[2]), "r"(a[3]), "r"(b0), "r"(b1));
}

__device__ __forceinline__ void ldmx4(uint32_t r[4], uint32_t addr) {
    asm volatile("ldmatrix.sync.aligned.m8n8.x4.shared.b16 {%0,%1,%2,%3}, [%4];"
                 : "=r"(r[0]), "=r"(r[1]), "=r"(r[2]), "=r"(r[3]) : "r"(addr));
}
__device__ __forceinline__ void ldmx4t(uint32_t r[4], uint32_t addr) {
    asm volatile("ldmatrix.sync.aligned.m8n8.x4.trans.shared.b16 {%0,%1,%2,%3}, [%4];"
                 : "=r"(r[0]), "=r"(r[1]), "=r"(r[2]), "=r"(r[3]) : "r"(addr));
}

__device__ __forceinline__ void cp_async16(uint32_t smem_dst, const void* gsrc) {
    asm volatile("cp.async.cg.shared.global [%0], [%1], 16;"
                 :: "r"(smem_dst), "l"(gsrc) : "memory");
}
__device__ __forceinline__ void cp_async_commit() {
    asm volatile("cp.async.commit_group;" ::: "memory");
}
__device__ __forceinline__ void cp_async_wait1() {
    asm volatile("cp.async.wait_group 1;" ::: "memory");
}

// ---------------------------------------------------------------------------
// Pre-pass 1: x (fp32, [8192][512]) -> g_xh fp16x2 words (packed along k).
// ---------------------------------------------------------------------------
__global__ __launch_bounds__(256)
void convert_x_kernel(const float4* __restrict__ x) {
    const int n4 = (ROWS * DMODEL) / 4;
    for (int i = blockIdx.x * blockDim.x + threadIdx.x; i < n4;
         i += gridDim.x * blockDim.x) {
        float4 v = x[i];
        g_xh[2 * i]     = h2pk(v.x, v.y);
        g_xh[2 * i + 1] = h2pk(v.z, v.w);
    }
}

// ---------------------------------------------------------------------------
// Pre-pass 2: W [K][N] fp32 -> Wt fp16x2 words [N][K/2] (packed along k).
// ---------------------------------------------------------------------------
__global__ __launch_bounds__(256)
void transpose_w_kernel(const float* __restrict__ W, uint32_t* __restrict__ Wt,
                        int K, int N) {
    __shared__ float tile[32][33];
    const int n0 = blockIdx.x * 32, k0 = blockIdx.y * 32;
    const int t = threadIdx.x;
    const int ln = t & 31, lk4 = (t >> 5) * 4;
    #pragma unroll
    for (int j = 0; j < 4; j++)
        tile[lk4 + j][ln] = W[(size_t)(k0 + lk4 + j) * N + n0 + ln];
    __syncthreads();
    const int Kw = K / 2;
    #pragma unroll
    for (int j = 0; j < 2; j++) {
        const int w = t * 2 + j;
        const int n = w >> 4, kw = w & 15;
        Wt[(size_t)(n0 + n) * Kw + (k0 >> 1) + kw] =
            h2pk(tile[2 * kw][n], tile[2 * kw + 1][n]);
    }
}

// ---------------------------------------------------------------------------
// FP16 tensor-core GEMM, 2-stage cp.async pipeline (exact R15 version).
// ---------------------------------------------------------------------------
#define HPAD 20
#define HW (128 * HPAD)

__global__ __launch_bounds__(256)
void h16_gemm_kernel(const uint32_t* __restrict__ A, const uint32_t* __restrict__ Bt,
                     void* __restrict__ C, int M, int N, int Kw, int out_fp16) {
    __shared__ uint32_t As[2][HW];
    __shared__ uint32_t Bs[2][HW];

    const int tid  = threadIdx.x;
    const int warp = tid >> 5;
    const int lane = tid & 31;
    const int g = lane >> 2;
    const int c = lane & 3;
    const int wm = warp >> 2;
    const int wn = warp & 3;

    const int lrow = tid >> 1, lcol = (tid & 1) << 3;

    const uint32_t* Ag = A  + (size_t)(blockIdx.y * 128 + lrow) * Kw + lcol;
    const uint32_t* Bg = Bt + (size_t)(blockIdx.x * 128 + lrow) * Kw + lcol;

    const uint32_t a_dst[2] = {
        (uint32_t)__cvta_generic_to_shared(&As[0][lrow * HPAD + lcol]),
        (uint32_t)__cvta_generic_to_shared(&As[1][lrow * HPAD + lcol]) };
    const uint32_t b_dst[2] = {
        (uint32_t)__cvta_generic_to_shared(&Bs[0][lrow * HPAD + lcol]),
        (uint32_t)__cvta_generic_to_shared(&Bs[1][lrow * HPAD + lcol]) };

    float acc[4][4][4];
    #pragma unroll
    for (int mf = 0; mf < 4; mf++)
        #pragma unroll
        for (int nf = 0; nf < 4; nf++)
            #pragma unroll
            for (int j = 0; j < 4; j++) acc[mf][nf][j] = 0.f;

    const int nIter = Kw / 16;

    cp_async16(a_dst[0],      Ag);
    cp_async16(a_dst[0] + 16, Ag + 4);
    cp_async16(b_dst[0],      Bg);
    cp_async16(b_dst[0] + 16, Bg + 4);
    cp_async_commit();

    for (int it = 0; it < nIter; it++) {
        const int cur = it & 1, nxt = cur ^ 1;

        if (it + 1 < nIter) {
            const int k0 = (it + 1) * 16;
            cp_async16(a_dst[nxt],      Ag + k0);
            cp_async16(a_dst[nxt] + 16, Ag + k0 + 4);
            cp_async16(b_dst[nxt],      Bg + k0);
            cp_async16(b_dst[nxt] + 16, Bg + k0 + 4);
        }
        cp_async_commit();
        cp_async_wait1();
        __syncthreads();

        const uint32_t* Asc = As[cur];
        const uint32_t* Bsc = Bs[cur];

        #pragma unroll
        for (int ch = 0; ch < 2; ch++) {
            uint32_t af[4][4], bf0[4], bf1[4];
            #pragma unroll
            for (int mf = 0; mf < 4; mf++) {
                const int r0 = wm * 64 + mf * 16 + g;
                af[mf][0] = Asc[(r0    ) * HPAD + ch * 8 + c    ];
                af[mf][1] = Asc[(r0 + 8) * HPAD + ch * 8 + c    ];
                af[mf][2] = Asc[(r0    ) * HPAD + ch * 8 + c + 4];
                af[mf][3] = Asc[(r0 + 8) * HPAD + ch * 8 + c + 4];
            }
            #pragma unroll
            for (int nf = 0; nf < 4; nf++) {
                const int n = wn * 32 + nf * 8 + g;
                bf0[nf] = Bsc[n * HPAD + ch * 8 + c    ];
                bf1[nf] = Bsc[n * HPAD + ch * 8 + c + 4];
            }
            #pragma unroll
            for (int mf = 0; mf < 4; mf++)
                #pragma unroll
                for (int nf = 0; nf < 4; nf++)
                    mma_f16(acc[mf][nf], af[mf], bf0[nf], bf1[nf]);
        }
        __syncthreads();
    }

    #pragma unroll
    for (int mf = 0; mf < 4; mf++) {
        const int r0 = blockIdx.y * 128 + wm * 64 + mf * 16 + g;
        #pragma unroll
        for (int nf = 0; nf < 4; nf++) {
            if (out_fp16) {
                uint32_t* Cw = (uint32_t*)C;
                const int wcol = blockIdx.x * 64 + wn * 16 + nf * 4 + c;
                Cw[(size_t)r0 * (N / 2) + wcol] =
                    h2pk(acc[mf][nf][0], acc[mf][nf][1]);
                Cw[(size_t)(r0 + 8) * (N / 2) + wcol] =
                    h2pk(acc[mf][nf][2], acc[mf][nf][3]);
            } else {
                float* Cf = (float*)C;
                const int col = blockIdx.x * 128 + wn * 32 + nf * 8 + 2 * c;
                *(float2*)&Cf[(size_t)r0 * N + col] =
                    make_float2(acc[mf][nf][0], acc[mf][nf][1]);
                *(float2*)&Cf[(size_t)(r0 + 8) * N + col] =
                    make_float2(acc[mf][nf][2], acc[mf][nf][3]);
            }
        }
    }
}

// ---------------------------------------------------------------------------
// FP16 flash attention with ldmatrix-fed MMAs.
// Block = 256 threads (8 warps), 128 queries of one (b,h'); 64-key tiles.
// qkv row = 96 words: Q 0..31, K 32..63, V 64..95 (fp16x2).
// K and V staged as plain row copies; QK B-frags via ldmatrix.x4,
// PV B-frags via ldmatrix.x4.trans (transpose done in the load unit).
// P stays in registers. Output fp16 words.
// ---------------------------------------------------------------------------
#define QP 36
#define KP 36
#define VP 36
#define QT 128

__global__ __launch_bounds__(256)
void attn_mma_kernel(const uint32_t* __restrict__ qkv, const int* __restrict__ pmask,
                     uint32_t* __restrict__ attout) {
    __shared__ uint32_t Qs[128 * QP];
    __shared__ uint32_t Ks[64 * KP];
    __shared__ uint32_t Vs[64 * VP];
    __shared__ float    mk[64];

    const int qt = blockIdx.x, h = blockIdx.y, b = blockIdx.z;
    const int tid  = threadIdx.x;
    const int warp = tid >> 5;
    const int lane = tid & 31;
    const int g = lane >> 2;
    const int c = lane & 3;

    const size_t rbase = (size_t)b * (NHEAD * SEQ) + (size_t)h * SEQ;
    const uint32_t* qkv_b = qkv + rbase * 96;

    const int qrow = tid >> 1, qsel = tid & 1;
    const int lrow = tid >> 2, fsel = tid & 3;

    // ldmatrix per-lane row addresses (byte addresses in shared space)
    const uint32_t Ks_s = (uint32_t)__cvta_generic_to_shared(Ks);
    const uint32_t Vs_s = (uint32_t)__cvta_generic_to_shared(Vs);
    const uint32_t kaddr0 = Ks_s + (uint32_t)(lane * KP) * 4;          // K rows 0..31
    const uint32_t kaddr1 = Ks_s + (uint32_t)((32 + lane) * KP) * 4;   // K rows 32..63
    const uint32_t vaddr  = Vs_s + (uint32_t)(((lane & 7) * VP + (lane >> 3) * 4)) * 4;

    // ---- stage Q tile (pure word copy) ----
    {
        const uint4* src = (const uint4*)(qkv_b + (size_t)(qt * QT + qrow) * 96 + qsel * 16);
        uint4* dst = (uint4*)&Qs[qrow * QP + qsel * 16];
        #pragma unroll
        for (int u = 0; u < 4; u++) dst[u] = src[u];
    }
    __syncthreads();

    // ---- Q fragments ----
    uint32_t qa[4][4];
    {
        const int r0 = warp * 16 + g;
        #pragma unroll
        for (int ch = 0; ch < 4; ch++) {
            qa[ch][0] = Qs[(r0    ) * QP + ch * 8 + c    ];
            qa[ch][1] = Qs[(r0 + 8) * QP + ch * 8 + c    ];
            qa[ch][2] = Qs[(r0    ) * QP + ch * 8 + c + 4];
            qa[ch][3] = Qs[(r0 + 8) * QP + ch * 8 + c + 4];
        }
    }

    float o[8][4];
    #pragma unroll
    for (int nf = 0; nf < 8; nf++)
        #pragma unroll
        for (int j = 0; j < 4; j++) o[nf][j] = 0.f;
    float m0 = -INFINITY, m1 = -INFINITY, l0 = 0.f, l1 = 0.f;

    for (int kt = 0; kt < SEQ / 64; kt++) {
        __syncthreads();

        // ---- stage K and V (plain row copies) + mask ----
        {
            const uint32_t* row = qkv_b + (size_t)(kt * 64 + lrow) * 96;
            const uint4* srck = (const uint4*)(row + 32 + fsel * 8);
            const uint4* srcv = (const uint4*)(row + 64 + fsel * 8);
            uint4* dk = (uint4*)&Ks[lrow * KP + fsel * 8];
            uint4* dv = (uint4*)&Vs[lrow * VP + fsel * 8];
            dk[0] = srck[0]; dk[1] = srck[1];
            dv[0] = srcv[0]; dv[1] = srcv[1];
            if (tid < 64)
                mk[tid] = (pmask[b * SEQ + kt * 64 + tid] != 0) ? 0.f : -INFINITY;
        }
        __syncthreads();

        // ---- S = Q K^T (ldmatrix-fed) ----
        float s[8][4];
        #pragma unroll
        for (int kg = 0; kg < 8; kg++)
            s[kg][0] = s[kg][1] = s[kg][2] = s[kg][3] = 0.f;

        #pragma unroll
        for (int ch = 0; ch < 4; ch++) {
            uint32_t kb0[4], kb1[4], kb2[4], kb3[4];
            ldmx4(kb0, kaddr0 + (uint32_t)(ch * 8) * 4);       // b0, kg 0..3
            ldmx4(kb1, kaddr0 + (uint32_t)(ch * 8 + 4) * 4);   // b1, kg 0..3
            ldmx4(kb2, kaddr1 + (uint32_t)(ch * 8) * 4);       // b0, kg 4..7
            ldmx4(kb3, kaddr1 + (uint32_t)(ch * 8 + 4) * 4);   // b1, kg 4..7
            #pragma unroll
            for (int kg = 0; kg < 4; kg++)
                mma_f16(s[kg], qa[ch], kb0[kg], kb1[kg]);
            #pragma unroll
            for (int kg = 0; kg < 4; kg++)
                mma_f16(s[kg + 4], qa[ch], kb2[kg], kb3[kg]);
        }

        // ---- scale + mask ----
        #pragma unroll
        for (int kg = 0; kg < 8; kg++) {
            const int col0 = kg * 8 + 2 * c;
            float mk0 = mk[col0], mk1 = mk[col0 + 1];
            s[kg][0] = s[kg][0] * 0.125f + mk0;
            s[kg][1] = s[kg][1] * 0.125f + mk1;
            s[kg][2] = s[kg][2] * 0.125f + mk0;
            s[kg][3] = s[kg][3] * 0.125f + mk1;
        }

        // ---- online softmax ----
        float mx0 = -INFINITY, mx1 = -INFINITY;
        #pragma unroll
        for (int kg = 0; kg < 8; kg++) {
            mx0 = fmaxf(mx0, fmaxf(s[kg][0], s[kg][1]));
            mx1 = fmaxf(mx1, fmaxf(s[kg][2], s[kg][3]));
        }
        mx0 = fmaxf(mx0, __shfl_xor_sync(0xffffffffu, mx0, 1));
        mx0 = fmaxf(mx0, __shfl_xor_sync(0xffffffffu, mx0, 2));
        mx1 = fmaxf(mx1, __shfl_xor_sync(0xffffffffu, mx1, 1));
        mx1 = fmaxf(mx1, __shfl_xor_sync(0xffffffffu, mx1, 2));

        float mn0 = fmaxf(m0, mx0), mn1 = fmaxf(m1, mx1);
        float sc0 = (mn0 == -INFINITY) ? 1.f : __expf(m0 - mn0);
        float sc1 = (mn1 == -INFINITY) ? 1.f : __expf(m1 - mn1);

        // ---- P in registers ----
        float sum0 = 0.f, sum1 = 0.f;
        uint32_t pa[4][4];
        #pragma unroll
        for (int ch = 0; ch < 4; ch++) {
            const int ke = 2 * ch, ko = 2 * ch + 1;
            float e0 = (s[ke][0] == -INFINITY) ? 0.f : __expf(s[ke][0] - mn0);
            float e1 = (s[ke][1] == -INFINITY) ? 0.f : __expf(s[ke][1] - mn0);
            float e2 = (s[ke][2] == -INFINITY) ? 0.f : __expf(s[ke][2] - mn1);
            float e3 = (s[ke][3] == -INFINITY) ? 0.f : __expf(s[ke][3] - mn1);
            float o0 = (s[ko][0] == -INFINITY) ? 0.f : __expf(s[ko][0] - mn0);
            float o1 = (s[ko][1] == -INFINITY) ? 0.f : __expf(s[ko][1] - mn0);
            float o2 = (s[ko][2] == -INFINITY) ? 0.f : __expf(s[ko][2] - mn1);
            float o3 = (s[ko][3] == -INFINITY) ? 0.f : __expf(s[ko][3] - mn1);
            sum0 += e0 + e1 + o0 + o1;
            sum1 += e2 + e3 + o2 + o3;
            pa[ch][0] = h2pk(e0, e1);
            pa[ch][1] = h2pk(e2, e3);
            pa[ch][2] = h2pk(o0, o1);
            pa[ch][3] = h2pk(o2, o3);
        }
        sum0 += __shfl_xor_sync(0xffffffffu, sum0, 1);
        sum0 += __shfl_xor_sync(0xffffffffu, sum0, 2);
        sum1 += __shfl_xor_sync(0xffffffffu, sum1, 1);
        sum1 += __shfl_xor_sync(0xffffffffu, sum1, 2);

        l0 = l0 * sc0 + sum0;  m0 = mn0;
        l1 = l1 * sc1 + sum1;  m1 = mn1;

        #pragma unroll
        for (int nf = 0; nf < 8; nf++) {
            o[nf][0] *= sc0; o[nf][1] *= sc0;
            o[nf][2] *= sc1; o[nf][3] *= sc1;
        }

        // ---- O += P V (trans-ldmatrix-fed) ----
        #pragma unroll
        for (int ch = 0; ch < 4; ch++) {
            uint32_t v0a[4], v0b[4], v1a[4], v1b[4];
            ldmx4t(v0a, vaddr + (uint32_t)((ch * 16    ) * VP     ) * 4);  // b0, nf 0..3
            ldmx4t(v0b, vaddr + (uint32_t)((ch * 16    ) * VP + 16) * 4);  // b0, nf 4..7
            ldmx4t(v1a, vaddr + (uint32_t)((ch * 16 + 8) * VP     ) * 4);  // b1, nf 0..3
            ldmx4t(v1b, vaddr + (uint32_t)((ch * 16 + 8) * VP + 16) * 4);  // b1, nf 4..7
            #pragma unroll
            for (int nf = 0; nf < 4; nf++)
                mma_f16(o[nf], pa[ch], v0a[nf], v1a[nf]);
            #pragma unroll
            for (int nf = 0; nf < 4; nf++)
                mma_f16(o[nf + 4], pa[ch], v0b[nf], v1b[nf]);
        }
    }

    // ---- epilogue: normalize, validity, store fp16 words ----
    {
        const int r0 = warp * 16 + g;
        const int row0 = qt * QT + r0, row1 = row0 + 8;
        float inv0 = (l0 > 0.f) ? (1.f / l0) : 0.f;
        float inv1 = (l1 > 0.f) ? (1.f / l1) : 0.f;
        if (pmask[b * SEQ + row0] == 0) inv0 = 0.f;
        if (pmask[b * SEQ + row1] == 0) inv1 = 0.f;
        uint32_t* out0 = attout + (rbase + row0) * (HDIM / 2) + c;
        uint32_t* out1 = attout + (rbase + row1) * (HDIM / 2) + c;
        #pragma unroll
        for (int nf = 0; nf < 8; nf++) {
            out0[nf * 4] = h2pk(o[nf][0] * inv0, o[nf][1] * inv0);
            out1[nf * 4] = h2pk(o[nf][2] * inv1, o[nf][3] * inv1);
        }
    }
}

// ---------------------------------------------------------------------------
extern "C" void kernel_launch(void* const* d_in, const int* in_sizes, int n_in,
                              void* d_out, int out_size) {
    const float* x     = (const float*)d_in[0];
    const int*   pmask = (const int*)d_in[2];
    const float* Wqkv  = (const float*)d_in[3];
    const float* Wout  = (const float*)d_in[4];
    float* out = (float*)d_out;

    uint32_t *qkvh_p, *atth_p, *xh_p, *wqt_p, *wot_p;
    cudaGetSymbolAddress((void**)&qkvh_p, g_qkvh);
    cudaGetSymbolAddress((void**)&atth_p, g_atth);
    cudaGetSymbolAddress((void**)&xh_p,   g_xh);
    cudaGetSymbolAddress((void**)&wqt_p,  g_wqt);
    cudaGetSymbolAddress((void**)&wot_p,  g_wot);

    // 0) pre-pass: x -> fp16; Wqkv, Wout -> transposed fp16
    convert_x_kernel<<<2048, 256>>>((const float4*)x);
    transpose_w_kernel<<<dim3(QKVN / 32, DMODEL / 32), 256>>>(Wqkv, wqt_p, DMODEL, QKVN);
    transpose_w_kernel<<<dim3(DMODEL / 32, DMODEL / 32), 256>>>(Wout, wot_p, DMODEL, DMODEL);

    // 1) QKV = x @ W_qkv (fp16 in/out): [8192,512] @ [512,1536]
    h16_gemm_kernel<<<dim3(QKVN / 128, ROWS / 128), 256>>>(
        xh_p, wqt_p, qkvh_p, ROWS, QKVN, DMODEL / 2, 1);

    // 2) fp16 attention over the reshaped (flat) layout
    attn_mma_kernel<<<dim3(SEQ / QT, NHEAD, BATCH), 256>>>(qkvh_p, pmask, atth_p);

    // 3) out = att @ W_out (fp32 out): [8192,512] @ [512,512]
    h16_gemm_kernel<<<dim3(DMODEL / 128, ROWS / 128), 256>>>(
        atth_p, wot_p, out, ROWS, DMODEL, DMODEL / 2, 0);
}

// round 17
// speedup vs baseline: 2.5752x; 1.0446x over previous
#include <cuda_runtime.h>
#include <cuda_fp16.h>
#include <math.h>
#include <stdint.h>

#define BATCH   4
#define SEQ     2048
#define DMODEL  512
#define NHEAD   8
#define HDIM    64
#define ROWS    (BATCH * SEQ)        /* 8192 */
#define QKVN    (3 * DMODEL)         /* 1536 */

// Scratch (allocation-free rule: device globals). fp16x2 word buffers.
__device__ uint32_t g_qkvh[(size_t)ROWS * (QKVN / 2)];    // [8192][768 words]
__device__ uint32_t g_atth[(size_t)ROWS * (DMODEL / 2)];  // [8192][256 words]
__device__ uint32_t g_xh  [(size_t)ROWS * (DMODEL / 2)];  // x as fp16 words
__device__ uint32_t g_wqt [(size_t)QKVN * (DMODEL / 2)];  // Wqkv^T [1536][256w]
__device__ uint32_t g_wot [(size_t)DMODEL * (DMODEL / 2)];// Wout^T [512][256w]

// pack two floats to fp16x2: low half = lo, high half = hi
__device__ __forceinline__ uint32_t h2pk(float lo, float hi) {
    uint32_t r;
    asm("cvt.rn.f16x2.f32 %0, %1, %2;" : "=r"(r) : "f"(hi), "f"(lo));
    return r;
}

__device__ __forceinline__ void mma_f16(float c[4], const uint32_t a[4],
                                        uint32_t b0, uint32_t b1) {
    asm volatile(
        "mma.sync.aligned.m16n8k16.row.col.f32.f16.f16.f32 "
        "{%0,%1,%2,%3}, {%4,%5,%6,%7}, {%8,%9}, {%0,%1,%2,%3};"
        : "+f"(c[0]), "+f"(c[1]), "+f"(c[2]), "+f"(c[3])
        : "r"(a[0]), "r"(a[1]), "r"(a[2]), "r"(a[3]), "r"(b0), "r"(b1));
}

__device__ __forceinline__ void ldmx4(uint32_t r[4], uint32_t addr) {
    asm volatile("ldmatrix.sync.aligned.m8n8.x4.shared.b16 {%0,%1,%2,%3}, [%4];"
                 : "=r"(r[0]), "=r"(r[1]), "=r"(r[2]), "=r"(r[3]) : "r"(addr));
}
__device__ __forceinline__ void ldmx4t(uint32_t r[4], uint32_t addr) {
    asm volatile("ldmatrix.sync.aligned.m8n8.x4.trans.shared.b16 {%0,%1,%2,%3}, [%4];"
                 : "=r"(r[0]), "=r"(r[1]), "=r"(r[2]), "=r"(r[3]) : "r"(addr));
}

__device__ __forceinline__ void cp_async16(uint32_t smem_dst, const void* gsrc) {
    asm volatile("cp.async.cg.shared.global [%0], [%1], 16;"
                 :: "r"(smem_dst), "l"(gsrc) : "memory");
}
__device__ __forceinline__ void cp_async_commit() {
    asm volatile("cp.async.commit_group;" ::: "memory");
}
__device__ __forceinline__ void cp_async_wait1() {
    asm volatile("cp.async.wait_group 1;" ::: "memory");
}

// ---------------------------------------------------------------------------
// Pre-pass 1: x (fp32, [8192][512]) -> g_xh fp16x2 words (packed along k).
// ---------------------------------------------------------------------------
__global__ __launch_bounds__(256)
void convert_x_kernel(const float4* __restrict__ x) {
    const int n4 = (ROWS * DMODEL) / 4;
    for (int i = blockIdx.x * blockDim.x + threadIdx.x; i < n4;
         i += gridDim.x * blockDim.x) {
        float4 v = x[i];
        g_xh[2 * i]     = h2pk(v.x, v.y);
        g_xh[2 * i + 1] = h2pk(v.z, v.w);
    }
}

// ---------------------------------------------------------------------------
// Pre-pass 2: W [K][N] fp32 -> Wt fp16x2 words [N][K/2] (packed along k).
// ---------------------------------------------------------------------------
__global__ __launch_bounds__(256)
void transpose_w_kernel(const float* __restrict__ W, uint32_t* __restrict__ Wt,
                        int K, int N) {
    __shared__ float tile[32][33];
    const int n0 = blockIdx.x * 32, k0 = blockIdx.y * 32;
    const int t = threadIdx.x;
    const int ln = t & 31, lk4 = (t >> 5) * 4;
    #pragma unroll
    for (int j = 0; j < 4; j++)
        tile[lk4 + j][ln] = W[(size_t)(k0 + lk4 + j) * N + n0 + ln];
    __syncthreads();
    const int Kw = K / 2;
    #pragma unroll
    for (int j = 0; j < 2; j++) {
        const int w = t * 2 + j;
        const int n = w >> 4, kw = w & 15;
        Wt[(size_t)(n0 + n) * Kw + (k0 >> 1) + kw] =
            h2pk(tile[2 * kw][n], tile[2 * kw + 1][n]);
    }
}

// ---------------------------------------------------------------------------
// FP16 tensor-core GEMM, 2-stage cp.async pipeline, ldmatrix-fed fragments.
// C[M,N] = A[M,K] @ B[K,N]; A fp16x2 words [M][Kw], B pre-transposed [N][Kw].
// 128x128 block tile, k=32/iter (2 chunks of k16), 8 warps, 64x32 warp tile.
// ---------------------------------------------------------------------------
#define HPAD 20
#define HW (128 * HPAD)

__global__ __launch_bounds__(256)
void h16_gemm_kernel(const uint32_t* __restrict__ A, const uint32_t* __restrict__ Bt,
                     void* __restrict__ C, int M, int N, int Kw, int out_fp16) {
    __shared__ __align__(16) uint32_t As[2][HW];
    __shared__ __align__(16) uint32_t Bs[2][HW];

    const int tid  = threadIdx.x;
    const int warp = tid >> 5;
    const int lane = tid & 31;
    const int g = lane >> 2;
    const int c = lane & 3;
    const int wm = warp >> 2;
    const int wn = warp & 3;

    const int lrow = tid >> 1, lcol = (tid & 1) << 3;

    const uint32_t* Ag = A  + (size_t)(blockIdx.y * 128 + lrow) * Kw + lcol;
    const uint32_t* Bg = Bt + (size_t)(blockIdx.x * 128 + lrow) * Kw + lcol;

    const uint32_t a_dst[2] = {
        (uint32_t)__cvta_generic_to_shared(&As[0][lrow * HPAD + lcol]),
        (uint32_t)__cvta_generic_to_shared(&As[1][lrow * HPAD + lcol]) };
    const uint32_t b_dst[2] = {
        (uint32_t)__cvta_generic_to_shared(&Bs[0][lrow * HPAD + lcol]),
        (uint32_t)__cvta_generic_to_shared(&Bs[1][lrow * HPAD + lcol]) };

    // ldmatrix lane addresses
    const uint32_t As_s = (uint32_t)__cvta_generic_to_shared(&As[0][0]);
    const uint32_t Bs_s = (uint32_t)__cvta_generic_to_shared(&Bs[0][0]);
    // A: row = wm*64 + mf*16 + (lane&15), col = ch*8 + (lane>>4)*4
    const uint32_t a_lm = (uint32_t)(((wm * 64 + (lane & 15)) * HPAD + (lane >> 4) * 4) * 4);
    // B: row = wn*32 + lane, col = ch*8 (+4 for b1)
    const uint32_t b_lm = (uint32_t)(((wn * 32 + lane) * HPAD) * 4);

    float acc[4][4][4];
    #pragma unroll
    for (int mf = 0; mf < 4; mf++)
        #pragma unroll
        for (int nf = 0; nf < 4; nf++)
            #pragma unroll
            for (int j = 0; j < 4; j++) acc[mf][nf][j] = 0.f;

    const int nIter = Kw / 16;

    cp_async16(a_dst[0],      Ag);
    cp_async16(a_dst[0] + 16, Ag + 4);
    cp_async16(b_dst[0],      Bg);
    cp_async16(b_dst[0] + 16, Bg + 4);
    cp_async_commit();

    for (int it = 0; it < nIter; it++) {
        const int cur = it & 1, nxt = cur ^ 1;

        if (it + 1 < nIter) {
            const int k0 = (it + 1) * 16;
            cp_async16(a_dst[nxt],      Ag + k0);
            cp_async16(a_dst[nxt] + 16, Ag + k0 + 4);
            cp_async16(b_dst[nxt],      Bg + k0);
            cp_async16(b_dst[nxt] + 16, Bg + k0 + 4);
        }
        cp_async_commit();
        cp_async_wait1();
        __syncthreads();

        const uint32_t abase = As_s + (uint32_t)(cur * HW * 4) + a_lm;
        const uint32_t bbase = Bs_s + (uint32_t)(cur * HW * 4) + b_lm;

        #pragma unroll
        for (int ch = 0; ch < 2; ch++) {
            uint32_t af[4][4], kb0[4], kb1[4];
            #pragma unroll
            for (int mf = 0; mf < 4; mf++)
                ldmx4(af[mf], abase + (uint32_t)((mf * 16 * HPAD + ch * 8) * 4));
            ldmx4(kb0, bbase + (uint32_t)((ch * 8    ) * 4));
            ldmx4(kb1, bbase + (uint32_t)((ch * 8 + 4) * 4));
            #pragma unroll
            for (int mf = 0; mf < 4; mf++)
                #pragma unroll
                for (int nf = 0; nf < 4; nf++)
                    mma_f16(acc[mf][nf], af[mf], kb0[nf], kb1[nf]);
        }
        __syncthreads();
    }

    #pragma unroll
    for (int mf = 0; mf < 4; mf++) {
        const int r0 = blockIdx.y * 128 + wm * 64 + mf * 16 + g;
        #pragma unroll
        for (int nf = 0; nf < 4; nf++) {
            if (out_fp16) {
                uint32_t* Cw = (uint32_t*)C;
                const int wcol = blockIdx.x * 64 + wn * 16 + nf * 4 + c;
                Cw[(size_t)r0 * (N / 2) + wcol] =
                    h2pk(acc[mf][nf][0], acc[mf][nf][1]);
                Cw[(size_t)(r0 + 8) * (N / 2) + wcol] =
                    h2pk(acc[mf][nf][2], acc[mf][nf][3]);
            } else {
                float* Cf = (float*)C;
                const int col = blockIdx.x * 128 + wn * 32 + nf * 8 + 2 * c;
                *(float2*)&Cf[(size_t)r0 * N + col] =
                    make_float2(acc[mf][nf][0], acc[mf][nf][1]);
                *(float2*)&Cf[(size_t)(r0 + 8) * N + col] =
                    make_float2(acc[mf][nf][2], acc[mf][nf][3]);
            }
        }
    }
}

// ---------------------------------------------------------------------------
// FP16 flash attention with ldmatrix-fed MMAs (R16 config; Q-frags now also
// via ldmatrix). Block = 256 threads (8 warps), 128 queries of one (b,h');
// 64-key tiles. qkv row = 96 words: Q 0..31, K 32..63, V 64..95 (fp16x2).
// ---------------------------------------------------------------------------
#define QP 36
#define KP 36
#define VP 36
#define QT 128

__global__ __launch_bounds__(256)
void attn_mma_kernel(const uint32_t* __restrict__ qkv, const int* __restrict__ pmask,
                     uint32_t* __restrict__ attout) {
    __shared__ __align__(16) uint32_t Qs[128 * QP];
    __shared__ __align__(16) uint32_t Ks[64 * KP];
    __shared__ __align__(16) uint32_t Vs[64 * VP];
    __shared__ float    mk[64];

    const int qt = blockIdx.x, h = blockIdx.y, b = blockIdx.z;
    const int tid  = threadIdx.x;
    const int warp = tid >> 5;
    const int lane = tid & 31;
    const int g = lane >> 2;
    const int c = lane & 3;

    const size_t rbase = (size_t)b * (NHEAD * SEQ) + (size_t)h * SEQ;
    const uint32_t* qkv_b = qkv + rbase * 96;

    const int qrow = tid >> 1, qsel = tid & 1;
    const int lrow = tid >> 2, fsel = tid & 3;

    const uint32_t Qs_s = (uint32_t)__cvta_generic_to_shared(Qs);
    const uint32_t Ks_s = (uint32_t)__cvta_generic_to_shared(Ks);
    const uint32_t Vs_s = (uint32_t)__cvta_generic_to_shared(Vs);
    const uint32_t qaddr  = Qs_s + (uint32_t)(((warp * 16 + (lane & 15)) * QP + (lane >> 4) * 4) * 4);
    const uint32_t kaddr0 = Ks_s + (uint32_t)(lane * KP) * 4;          // K rows 0..31
    const uint32_t kaddr1 = Ks_s + (uint32_t)((32 + lane) * KP) * 4;   // K rows 32..63
    const uint32_t vaddr  = Vs_s + (uint32_t)(((lane & 7) * VP + (lane >> 3) * 4)) * 4;

    // ---- stage Q tile (pure word copy) ----
    {
        const uint4* src = (const uint4*)(qkv_b + (size_t)(qt * QT + qrow) * 96 + qsel * 16);
        uint4* dst = (uint4*)&Qs[qrow * QP + qsel * 16];
        #pragma unroll
        for (int u = 0; u < 4; u++) dst[u] = src[u];
    }
    __syncthreads();

    // ---- Q fragments via ldmatrix ----
    uint32_t qa[4][4];
    #pragma unroll
    for (int ch = 0; ch < 4; ch++)
        ldmx4(qa[ch], qaddr + (uint32_t)(ch * 8 * 4));

    float o[8][4];
    #pragma unroll
    for (int nf = 0; nf < 8; nf++)
        #pragma unroll
        for (int j = 0; j < 4; j++) o[nf][j] = 0.f;
    float m0 = -INFINITY, m1 = -INFINITY, l0 = 0.f, l1 = 0.f;

    for (int kt = 0; kt < SEQ / 64; kt++) {
        __syncthreads();

        // ---- stage K and V (plain row copies) + mask ----
        {
            const uint32_t* row = qkv_b + (size_t)(kt * 64 + lrow) * 96;
            const uint4* srck = (const uint4*)(row + 32 + fsel * 8);
            const uint4* srcv = (const uint4*)(row + 64 + fsel * 8);
            uint4* dk = (uint4*)&Ks[lrow * KP + fsel * 8];
            uint4* dv = (uint4*)&Vs[lrow * VP + fsel * 8];
            dk[0] = srck[0]; dk[1] = srck[1];
            dv[0] = srcv[0]; dv[1] = srcv[1];
            if (tid < 64)
                mk[tid] = (pmask[b * SEQ + kt * 64 + tid] != 0) ? 0.f : -INFINITY;
        }
        __syncthreads();

        // ---- S = Q K^T (ldmatrix-fed) ----
        float s[8][4];
        #pragma unroll
        for (int kg = 0; kg < 8; kg++)
            s[kg][0] = s[kg][1] = s[kg][2] = s[kg][3] = 0.f;

        #pragma unroll
        for (int ch = 0; ch < 4; ch++) {
            uint32_t kb0[4], kb1[4], kb2[4], kb3[4];
            ldmx4(kb0, kaddr0 + (uint32_t)(ch * 8) * 4);
            ldmx4(kb1, kaddr0 + (uint32_t)(ch * 8 + 4) * 4);
            ldmx4(kb2, kaddr1 + (uint32_t)(ch * 8) * 4);
            ldmx4(kb3, kaddr1 + (uint32_t)(ch * 8 + 4) * 4);
            #pragma unroll
            for (int kg = 0; kg < 4; kg++)
                mma_f16(s[kg], qa[ch], kb0[kg], kb1[kg]);
            #pragma unroll
            for (int kg = 0; kg < 4; kg++)
                mma_f16(s[kg + 4], qa[ch], kb2[kg], kb3[kg]);
        }

        // ---- scale + mask ----
        #pragma unroll
        for (int kg = 0; kg < 8; kg++) {
            const int col0 = kg * 8 + 2 * c;
            float mk0 = mk[col0], mk1 = mk[col0 + 1];
            s[kg][0] = s[kg][0] * 0.125f + mk0;
            s[kg][1] = s[kg][1] * 0.125f + mk1;
            s[kg][2] = s[kg][2] * 0.125f + mk0;
            s[kg][3] = s[kg][3] * 0.125f + mk1;
        }

        // ---- online softmax ----
        float mx0 = -INFINITY, mx1 = -INFINITY;
        #pragma unroll
        for (int kg = 0; kg < 8; kg++) {
            mx0 = fmaxf(mx0, fmaxf(s[kg][0], s[kg][1]));
            mx1 = fmaxf(mx1, fmaxf(s[kg][2], s[kg][3]));
        }
        mx0 = fmaxf(mx0, __shfl_xor_sync(0xffffffffu, mx0, 1));
        mx0 = fmaxf(mx0, __shfl_xor_sync(0xffffffffu, mx0, 2));
        mx1 = fmaxf(mx1, __shfl_xor_sync(0xffffffffu, mx1, 1));
        mx1 = fmaxf(mx1, __shfl_xor_sync(0xffffffffu, mx1, 2));

        float mn0 = fmaxf(m0, mx0), mn1 = fmaxf(m1, mx1);
        float sc0 = (mn0 == -INFINITY) ? 1.f : __expf(m0 - mn0);
        float sc1 = (mn1 == -INFINITY) ? 1.f : __expf(m1 - mn1);

        // ---- P in registers ----
        float sum0 = 0.f, sum1 = 0.f;
        uint32_t pa[4][4];
        #pragma unroll
        for (int ch = 0; ch < 4; ch++) {
            const int ke = 2 * ch, ko = 2 * ch + 1;
            float e0 = (s[ke][0] == -INFINITY) ? 0.f : __expf(s[ke][0] - mn0);
            float e1 = (s[ke][1] == -INFINITY) ? 0.f : __expf(s[ke][1] - mn0);
            float e2 = (s[ke][2] == -INFINITY) ? 0.f : __expf(s[ke][2] - mn1);
            float e3 = (s[ke][3] == -INFINITY) ? 0.f : __expf(s[ke][3] - mn1);
            float o0 = (s[ko][0] == -INFINITY) ? 0.f : __expf(s[ko][0] - mn0);
            float o1 = (s[ko][1] == -INFINITY) ? 0.f : __expf(s[ko][1] - mn0);
            float o2 = (s[ko][2] == -INFINITY) ? 0.f : __expf(s[ko][2] - mn1);
            float o3 = (s[ko][3] == -INFINITY) ? 0.f : __expf(s[ko][3] - mn1);
            sum0 += e0 + e1 + o0 + o1;
            sum1 += e2 + e3 + o2 + o3;
            pa[ch][0] = h2pk(e0, e1);
            pa[ch][1] = h2pk(e2, e3);
            pa[ch][2] = h2pk(o0, o1);
            pa[ch][3] = h2pk(o2, o3);
        }
        sum0 += __shfl_xor_sync(0xffffffffu, sum0, 1);
        sum0 += __shfl_xor_sync(0xffffffffu, sum0, 2);
        sum1 += __shfl_xor_sync(0xffffffffu, sum1, 1);
        sum1 += __shfl_xor_sync(0xffffffffu, sum1, 2);

        l0 = l0 * sc0 + sum0;  m0 = mn0;
        l1 = l1 * sc1 + sum1;  m1 = mn1;

        #pragma unroll
        for (int nf = 0; nf < 8; nf++) {
            o[nf][0] *= sc0; o[nf][1] *= sc0;
            o[nf][2] *= sc1; o[nf][3] *= sc1;
        }

        // ---- O += P V (trans-ldmatrix-fed) ----
        #pragma unroll
        for (int ch = 0; ch < 4; ch++) {
            uint32_t v0a[4], v0b[4], v1a[4], v1b[4];
            ldmx4t(v0a, vaddr + (uint32_t)((ch * 16    ) * VP     ) * 4);
            ldmx4t(v0b, vaddr + (uint32_t)((ch * 16    ) * VP + 16) * 4);
            ldmx4t(v1a, vaddr + (uint32_t)((ch * 16 + 8) * VP     ) * 4);
            ldmx4t(v1b, vaddr + (uint32_t)((ch * 16 + 8) * VP + 16) * 4);
            #pragma unroll
            for (int nf = 0; nf < 4; nf++)
                mma_f16(o[nf], pa[ch], v0a[nf], v1a[nf]);
            #pragma unroll
            for (int nf = 0; nf < 4; nf++)
                mma_f16(o[nf + 4], pa[ch], v0b[nf], v1b[nf]);
        }
    }

    // ---- epilogue: normalize, validity, store fp16 words ----
    {
        const int r0 = warp * 16 + g;
        const int row0 = qt * QT + r0, row1 = row0 + 8;
        float inv0 = (l0 > 0.f) ? (1.f / l0) : 0.f;
        float inv1 = (l1 > 0.f) ? (1.f / l1) : 0.f;
        if (pmask[b * SEQ + row0] == 0) inv0 = 0.f;
        if (pmask[b * SEQ + row1] == 0) inv1 = 0.f;
        uint32_t* out0 = attout + (rbase + row0) * (HDIM / 2) + c;
        uint32_t* out1 = attout + (rbase + row1) * (HDIM / 2) + c;
        #pragma unroll
        for (int nf = 0; nf < 8; nf++) {
            out0[nf * 4] = h2pk(o[nf][0] * inv0, o[nf][1] * inv0);
            out1[nf * 4] = h2pk(o[nf][2] * inv1, o[nf][3] * inv1);
        }
    }
}

// ---------------------------------------------------------------------------
extern "C" void kernel_launch(void* const* d_in, const int* in_sizes, int n_in,
                              void* d_out, int out_size) {
    const float* x     = (const float*)d_in[0];
    const int*   pmask = (const int*)d_in[2];
    const float* Wqkv  = (const float*)d_in[3];
    const float* Wout  = (const float*)d_in[4];
    float* out = (float*)d_out;

    uint32_t *qkvh_p, *atth_p, *xh_p, *wqt_p, *wot_p;
    cudaGetSymbolAddress((void**)&qkvh_p, g_qkvh);
    cudaGetSymbolAddress((void**)&atth_p, g_atth);
    cudaGetSymbolAddress((void**)&xh_p,   g_xh);
    cudaGetSymbolAddress((void**)&wqt_p,  g_wqt);
    cudaGetSymbolAddress((void**)&wot_p,  g_wot);

    // 0) pre-pass: x -> fp16; Wqkv, Wout -> transposed fp16
    convert_x_kernel<<<2048, 256>>>((const float4*)x);
    transpose_w_kernel<<<dim3(QKVN / 32, DMODEL / 32), 256>>>(Wqkv, wqt_p, DMODEL, QKVN);
    transpose_w_kernel<<<dim3(DMODEL / 32, DMODEL / 32), 256>>>(Wout, wot_p, DMODEL, DMODEL);

    // 1) QKV = x @ W_qkv (fp16 in/out): [8192,512] @ [512,1536]
    h16_gemm_kernel<<<dim3(QKVN / 128, ROWS / 128), 256>>>(
        xh_p, wqt_p, qkvh_p, ROWS, QKVN, DMODEL / 2, 1);

    // 2) fp16 attention over the reshaped (flat) layout
    attn_mma_kernel<<<dim3(SEQ / QT, NHEAD, BATCH), 256>>>(qkvh_p, pmask, atth_p);

    // 3) out = att @ W_out (fp32 out): [8192,512] @ [512,512]
    h16_gemm_kernel<<<dim3(DMODEL / 128, ROWS / 128), 256>>>(
        atth_p, wot_p, out, ROWS, DMODEL, DMODEL / 2, 0);
}